// round 1
// baseline (speedup 1.0000x reference)
#include <cuda_runtime.h>
#include <math.h>

#define NSEQ 64          // B*C
#define TT   256         // T
#define FF   64          // F
#define DMM  128         // d_model
#define DII  256         // d_inner
#define DSS  16          // d_state
#define DTRR 8           // dt_rank
#define ROWS (NSEQ*TT)   // 16384
#define LNEPS 1e-5f

// ---------------- scratch (static device memory; no dynamic alloc) ----------------
__device__ float g_h   [ROWS*DMM];       //  8 MB  residual stream
__device__ float g_xz  [ROWS*2*DII];     // 32 MB  in_proj output (xi | z)
__device__ float g_u   [ROWS*DII];       // 16 MB  conv+silu output
__device__ float g_xdbl[ROWS*40];        //  2.6MB x_proj output (dt8|B16|C16)
__device__ float g_ym  [ROWS*DII];       // 16 MB  gated scan output
__device__ float g_yo  [ROWS*DMM];       //  8 MB  out_proj output
__device__ float g_part[NSEQ*4*DMM];     // final partial sums

// ---------------- helpers ----------------
__device__ __forceinline__ void row_stats128(float v, float& mu, float& var) {
    // blockDim.x == 128 assumed
    float s = v, q = v * v;
    #pragma unroll
    for (int o = 16; o; o >>= 1) {
        s += __shfl_down_sync(0xffffffffu, s, o);
        q += __shfl_down_sync(0xffffffffu, q, o);
    }
    __shared__ float ss[4], sq[4];
    int w = threadIdx.x >> 5;
    if ((threadIdx.x & 31) == 0) { ss[w] = s; sq[w] = q; }
    __syncthreads();
    s = ss[0] + ss[1] + ss[2] + ss[3];
    q = sq[0] + sq[1] + sq[2] + sq[3];
    __syncthreads();
    mu  = s * (1.0f / DMM);
    var = q * (1.0f / DMM) - mu * mu;
}

// ---------------- input projection: h[n,t,:] = x[b,c,:,t] @ inp_w^T + inp_b ----------------
__global__ void __launch_bounds__(128) input_proj_kernel(
    const float* __restrict__ x, const float* __restrict__ w, const float* __restrict__ b)
{
    int n = blockIdx.x, t0 = blockIdx.y * 64, d = threadIdx.x;
    __shared__ float xsT[FF][64];  // [f][t]
    float wreg[FF];
    #pragma unroll
    for (int f = 0; f < FF; f++) wreg[f] = w[d * FF + f];
    float bias = b[d];
    for (int idx = threadIdx.x; idx < FF * 64; idx += 128) {
        int f = idx >> 6, tt = idx & 63;
        xsT[f][tt] = x[(size_t)n * FF * TT + (size_t)f * TT + t0 + tt];
    }
    __syncthreads();
    for (int tt = 0; tt < 64; tt++) {
        float acc = bias;
        #pragma unroll
        for (int f = 0; f < FF; f++) acc += wreg[f] * xsT[f][tt];
        g_h[(size_t)(n * TT + t0 + tt) * DMM + d] = acc;
    }
}

// ---------------- generic GEMM: C[M,N] = A[M,K] @ B[N,K]^T ----------------
// M multiple of 64, K multiple of 16, N guarded.
__global__ void __launch_bounds__(256) gemm_tn_kernel(
    const float* __restrict__ A, const float* __restrict__ B, float* __restrict__ C,
    int M, int N, int K)
{
    const int BM = 64, BN = 64, BK = 16;
    __shared__ float As[BK][BM];
    __shared__ float Bs[BK][BN];
    int bm = blockIdx.x * BM, bn = blockIdx.y * BN;
    int tid = threadIdx.x;
    int tm = (tid >> 4) << 2, tn = (tid & 15) << 2;
    int lrow = tid >> 2, lcol = (tid & 3) << 2;
    float acc[4][4] = {};
    for (int k0 = 0; k0 < K; k0 += BK) {
        float4 av = *(const float4*)(A + (size_t)(bm + lrow) * K + k0 + lcol);
        As[lcol + 0][lrow] = av.x; As[lcol + 1][lrow] = av.y;
        As[lcol + 2][lrow] = av.z; As[lcol + 3][lrow] = av.w;
        float4 bv = make_float4(0.f, 0.f, 0.f, 0.f);
        if (bn + lrow < N)
            bv = *(const float4*)(B + (size_t)(bn + lrow) * K + k0 + lcol);
        Bs[lcol + 0][lrow] = bv.x; Bs[lcol + 1][lrow] = bv.y;
        Bs[lcol + 2][lrow] = bv.z; Bs[lcol + 3][lrow] = bv.w;
        __syncthreads();
        #pragma unroll
        for (int k = 0; k < BK; k++) {
            float4 a4 = *(const float4*)&As[k][tm];
            float4 b4 = *(const float4*)&Bs[k][tn];
            acc[0][0] += a4.x * b4.x; acc[0][1] += a4.x * b4.y; acc[0][2] += a4.x * b4.z; acc[0][3] += a4.x * b4.w;
            acc[1][0] += a4.y * b4.x; acc[1][1] += a4.y * b4.y; acc[1][2] += a4.y * b4.z; acc[1][3] += a4.y * b4.w;
            acc[2][0] += a4.z * b4.x; acc[2][1] += a4.z * b4.y; acc[2][2] += a4.z * b4.z; acc[2][3] += a4.z * b4.w;
            acc[3][0] += a4.w * b4.x; acc[3][1] += a4.w * b4.y; acc[3][2] += a4.w * b4.z; acc[3][3] += a4.w * b4.w;
        }
        __syncthreads();
    }
    #pragma unroll
    for (int i = 0; i < 4; i++) {
        #pragma unroll
        for (int j = 0; j < 4; j++) {
            if (bn + tn + j < N)
                C[(size_t)(bm + tm + i) * N + bn + tn + j] = acc[i][j];
        }
    }
}

// ---------------- causal depthwise conv (k=4) + silu: reads xi half of g_xz ----------------
__global__ void __launch_bounds__(256) conv_silu_kernel(
    const float* __restrict__ cw, const float* __restrict__ cb)
{
    int n = blockIdx.x, t0 = blockIdx.y * 64, d = threadIdx.x;
    float w0 = cw[d * 4 + 0], w1 = cw[d * 4 + 1], w2 = cw[d * 4 + 2], w3 = cw[d * 4 + 3];
    float bias = cb[d];
    float x0 = (t0 - 3 >= 0) ? g_xz[(size_t)(n * TT + t0 - 3) * 2 * DII + d] : 0.f;
    float x1 = (t0 - 2 >= 0) ? g_xz[(size_t)(n * TT + t0 - 2) * 2 * DII + d] : 0.f;
    float x2 = (t0 - 1 >= 0) ? g_xz[(size_t)(n * TT + t0 - 1) * 2 * DII + d] : 0.f;
    for (int tt = 0; tt < 64; tt++) {
        float x3 = g_xz[(size_t)(n * TT + t0 + tt) * 2 * DII + d];
        float s = w0 * x0 + w1 * x1 + w2 * x2 + w3 * x3 + bias;
        float u = s / (1.f + __expf(-s));     // silu
        g_u[(size_t)(n * TT + t0 + tt) * DII + d] = u;
        x0 = x1; x1 = x2; x2 = x3;
    }
}

// ---------------- selective scan (fused dt-proj + softplus + gating) ----------------
// grid (NSEQ, 2), 128 threads; thread owns channel d = by*128+tid, 16 states in regs.
__global__ void __launch_bounds__(128) scan_kernel(
    const float* __restrict__ dtw, const float* __restrict__ dtb,
    const float* __restrict__ alog, const float* __restrict__ Dv)
{
    int n = blockIdx.x;
    int tid = threadIdx.x;
    int d = blockIdx.y * 128 + tid;

    float A[DSS], hst[DSS], wdt[DTRR];
    #pragma unroll
    for (int s = 0; s < DSS; s++) { A[s] = -__expf(alog[d * DSS + s]); hst[s] = 0.f; }
    #pragma unroll
    for (int j = 0; j < DTRR; j++) wdt[j] = dtw[d * DTRR + j];
    float dtbd = dtb[d], Dd = Dv[d];

    __shared__ float sx[3][48];  // triple-buffered (dt8 | B16 | C16) per timestep

    const size_t base_u = (size_t)n * TT * DII + d;
    const size_t base_z = (size_t)n * TT * 2 * DII + DII + d;
    const size_t base_x = (size_t)n * TT * 40;

    // preload t=0,1 (prefetch distance 2 hides L2 latency)
    float u_a = g_u[base_u],        z_a = g_xz[base_z];
    float u_b = g_u[base_u + DII],  z_b = g_xz[base_z + 2 * DII];
    if (tid < 40) {
        sx[0][tid] = g_xdbl[base_x + tid];
        sx[1][tid] = g_xdbl[base_x + 40 + tid];
    }
    __syncthreads();

    for (int t = 0; t < TT; t++) {
        float u_n = 0.f, z_n = 0.f;
        if (t + 2 < TT) {
            u_n = g_u[base_u + (size_t)(t + 2) * DII];
            z_n = g_xz[base_z + (size_t)(t + 2) * 2 * DII];
            if (tid < 40)
                sx[(t + 2) % 3][tid] = g_xdbl[base_x + (size_t)(t + 2) * 40 + tid];
        }
        const float* sc = sx[t % 3];
        // delta = softplus(dt @ dt_w^T + dt_b)
        float dtv = dtbd;
        #pragma unroll
        for (int j = 0; j < DTRR; j++) dtv += sc[j] * wdt[j];
        float delta = (dtv > 15.f) ? dtv : log1pf(__expf(dtv));
        float du = delta * u_a;
        float y = 0.f;
        #pragma unroll
        for (int s = 0; s < DSS; s++) {
            float e = __expf(delta * A[s]);
            hst[s] = e * hst[s] + du * sc[8 + s];
            y += hst[s] * sc[24 + s];
        }
        y += u_a * Dd;
        float sz = z_a / (1.f + __expf(-z_a));   // silu(z)
        g_ym[base_u + (size_t)t * DII] = y * sz;
        u_a = u_b; z_a = z_b; u_b = u_n; z_b = z_n;
        __syncthreads();
    }
}

// ---------------- residual add + layernorm (in place on g_h) ----------------
__global__ void __launch_bounds__(128) res_ln_kernel(
    const float* __restrict__ nw, const float* __restrict__ nb)
{
    size_t r = blockIdx.x;
    int d = threadIdx.x;
    float v = g_h[r * DMM + d] + g_yo[r * DMM + d];
    float mu, var;
    row_stats128(v, mu, var);
    g_h[r * DMM + d] = (v - mu) * rsqrtf(var + LNEPS) * nw[d] + nb[d];
}

// ---------------- final layernorm + mean over T (partials, then combine) ----------------
__global__ void __launch_bounds__(128) final_partial_kernel(
    const float* __restrict__ w, const float* __restrict__ b)
{
    int n = blockIdx.x, t0 = blockIdx.y * 64, d = threadIdx.x;
    float wd = w[d], bd = b[d], acc = 0.f;
    for (int tt = 0; tt < 64; tt++) {
        float v = g_h[(size_t)(n * TT + t0 + tt) * DMM + d];
        float mu, var;
        row_stats128(v, mu, var);
        acc += (v - mu) * rsqrtf(var + LNEPS) * wd + bd;
    }
    g_part[(size_t)(n * 4 + blockIdx.y) * DMM + d] = acc;
}

__global__ void __launch_bounds__(128) final_combine_kernel(float* __restrict__ out)
{
    int n = blockIdx.x, d = threadIdx.x;
    float s = g_part[(size_t)(n * 4 + 0) * DMM + d]
            + g_part[(size_t)(n * 4 + 1) * DMM + d]
            + g_part[(size_t)(n * 4 + 2) * DMM + d]
            + g_part[(size_t)(n * 4 + 3) * DMM + d];
    out[(size_t)n * DMM + d] = s * (1.0f / TT);
}

// ---------------- launch ----------------
extern "C" void kernel_launch(void* const* d_in, const int* in_sizes, int n_in,
                              void* d_out, int out_size)
{
    (void)in_sizes; (void)n_in; (void)out_size;
    const float* x     = (const float*)d_in[0];
    const float* inp_w = (const float*)d_in[1];
    const float* inp_b = (const float*)d_in[2];
    const float* ipw   = (const float*)d_in[3];   // [2,512,128]
    const float* cw    = (const float*)d_in[4];   // [2,256,4]
    const float* cb    = (const float*)d_in[5];   // [2,256]
    const float* xpw   = (const float*)d_in[6];   // [2,40,256]
    const float* dtw   = (const float*)d_in[7];   // [2,256,8]
    const float* dtb   = (const float*)d_in[8];   // [2,256]
    const float* alog  = (const float*)d_in[9];   // [2,256,16]
    const float* Dv    = (const float*)d_in[10];  // [2,256]
    const float* opw   = (const float*)d_in[11];  // [2,128,256]
    const float* nw    = (const float*)d_in[12];  // [2,128]
    const float* nb    = (const float*)d_in[13];  // [2,128]
    const float* onw   = (const float*)d_in[14];  // [128]
    const float* onb   = (const float*)d_in[15];  // [128]
    float* out = (float*)d_out;

    float *ph, *pxz, *pu, *pxd, *pym, *pyo;
    cudaGetSymbolAddress((void**)&ph,  g_h);
    cudaGetSymbolAddress((void**)&pxz, g_xz);
    cudaGetSymbolAddress((void**)&pu,  g_u);
    cudaGetSymbolAddress((void**)&pxd, g_xdbl);
    cudaGetSymbolAddress((void**)&pym, g_ym);
    cudaGetSymbolAddress((void**)&pyo, g_yo);

    input_proj_kernel<<<dim3(NSEQ, 4), 128>>>(x, inp_w, inp_b);

    for (int l = 0; l < 2; l++) {
        // xz = h @ in_proj_w^T           [16384,512]
        gemm_tn_kernel<<<dim3(ROWS / 64, 8), 256>>>(ph, ipw + (size_t)l * 2 * DII * DMM, pxz,
                                                    ROWS, 2 * DII, DMM);
        // u = silu(causal_conv(xi) + b)  [16384,256]
        conv_silu_kernel<<<dim3(NSEQ, 4), 256>>>(cw + (size_t)l * DII * 4, cb + (size_t)l * DII);
        // x_dbl = u @ x_proj_w^T         [16384,40]
        gemm_tn_kernel<<<dim3(ROWS / 64, 1), 256>>>(pu, xpw + (size_t)l * 40 * DII, pxd,
                                                    ROWS, 40, DII);
        // fused dt-proj + softplus + selective scan + D skip + silu(z) gate
        scan_kernel<<<dim3(NSEQ, 2), 128>>>(dtw + (size_t)l * DII * DTRR, dtb + (size_t)l * DII,
                                            alog + (size_t)l * DII * DSS, Dv + (size_t)l * DII);
        // yo = ym @ out_proj_w^T         [16384,128]
        gemm_tn_kernel<<<dim3(ROWS / 64, 2), 256>>>(pym, opw + (size_t)l * DMM * DII, pyo,
                                                    ROWS, DMM, DII);
        // h = LN(h + yo)
        res_ln_kernel<<<ROWS, 128>>>(nw + (size_t)l * DMM, nb + (size_t)l * DMM);
    }

    final_partial_kernel<<<dim3(NSEQ, 4), 128>>>(onw, onb);
    final_combine_kernel<<<NSEQ, 128>>>(out);
}

// round 2
// speedup vs baseline: 1.3577x; 1.3577x over previous
#include <cuda_runtime.h>
#include <math.h>
#include <stdint.h>

#define NSEQ 64          // B*C
#define TT   256         // T
#define FF   64          // F
#define DMM  128         // d_model
#define DII  256         // d_inner
#define DSS  16          // d_state
#define DTRR 8           // dt_rank
#define ROWS (NSEQ*TT)   // 16384
#define LNEPS 1e-5f

// ---------------- scratch (static device memory) ----------------
__device__ float g_h   [ROWS*DMM];
__device__ float g_xz  [ROWS*2*DII];
__device__ float g_u   [ROWS*DII];
__device__ float g_xdbl[ROWS*40];
__device__ float g_ym  [ROWS*DII];
__device__ float g_yo  [ROWS*DMM];
__device__ float g_part[NSEQ*4*DMM];

// ---------------- helpers ----------------
__device__ __forceinline__ uint32_t smem_u32(const void* p) {
    return (uint32_t)__cvta_generic_to_shared(p);
}

__device__ __forceinline__ void mma_tf32(float* c, const uint32_t* a, const uint32_t* b) {
    asm volatile(
        "mma.sync.aligned.m16n8k8.row.col.f32.tf32.tf32.f32 "
        "{%0,%1,%2,%3}, {%4,%5,%6,%7}, {%8,%9}, {%0,%1,%2,%3};"
        : "+f"(c[0]), "+f"(c[1]), "+f"(c[2]), "+f"(c[3])
        : "r"(a[0]), "r"(a[1]), "r"(a[2]), "r"(a[3]), "r"(b[0]), "r"(b[1]));
}

__device__ __forceinline__ void row_stats128(float v, float& mu, float& var) {
    float s = v, q = v * v;
    #pragma unroll
    for (int o = 16; o; o >>= 1) {
        s += __shfl_down_sync(0xffffffffu, s, o);
        q += __shfl_down_sync(0xffffffffu, q, o);
    }
    __shared__ float ss[4], sq[4];
    int w = threadIdx.x >> 5;
    if ((threadIdx.x & 31) == 0) { ss[w] = s; sq[w] = q; }
    __syncthreads();
    s = ss[0] + ss[1] + ss[2] + ss[3];
    q = sq[0] + sq[1] + sq[2] + sq[3];
    __syncthreads();
    mu  = s * (1.0f / DMM);
    var = q * (1.0f / DMM) - mu * mu;
}

// ---------------- input projection ----------------
__global__ void __launch_bounds__(128) input_proj_kernel(
    const float* __restrict__ x, const float* __restrict__ w, const float* __restrict__ b)
{
    int n = blockIdx.x, t0 = blockIdx.y * 64, d = threadIdx.x;
    __shared__ float xsT[FF][64];
    float wreg[FF];
    #pragma unroll
    for (int f = 0; f < FF; f++) wreg[f] = w[d * FF + f];
    float bias = b[d];
    for (int idx = threadIdx.x; idx < FF * 64; idx += 128) {
        int f = idx >> 6, tt = idx & 63;
        xsT[f][tt] = x[(size_t)n * FF * TT + (size_t)f * TT + t0 + tt];
    }
    __syncthreads();
    for (int tt = 0; tt < 64; tt++) {
        float acc = bias;
        #pragma unroll
        for (int f = 0; f < FF; f++) acc += wreg[f] * xsT[f][tt];
        g_h[(size_t)(n * TT + t0 + tt) * DMM + d] = acc;
    }
}

// ---------------- tf32 tensor-core GEMM: C[M,N] = A[M,K] @ B[N,K]^T ----------------
// BM=128, BN=64, BK=16. 256 threads = 8 warps in a 4x2 grid, warp tile 32x32.
// M mult of 128, K mult of 16, N guarded (rows >= N zero-filled; N mult of 8).
__global__ void __launch_bounds__(256) mma_gemm_kernel(
    const float* __restrict__ A, const float* __restrict__ B, float* __restrict__ C,
    int M, int N, int K)
{
    const int BM = 128, BN = 64, BK = 16;
    __shared__ float As[2][BM][BK + 4];   // pad 20 floats/row -> conflict-free
    __shared__ float Bs[2][BN][BK + 4];

    int tid  = threadIdx.x;
    int bm   = blockIdx.x * BM, bn = blockIdx.y * BN;
    int warp = tid >> 5, lane = tid & 31;
    int gid  = lane >> 2, tig = lane & 3;
    int m0   = (warp & 3) * 32;
    int n0   = (warp >> 2) * 32;

    float acc[2][4][4];
    #pragma unroll
    for (int i = 0; i < 2; i++)
        #pragma unroll
        for (int j = 0; j < 4; j++)
            #pragma unroll
            for (int k = 0; k < 4; k++) acc[i][j][k] = 0.f;

    int arow = tid >> 1, akq = (tid & 1) * 4;   // A copy: 128 rows x 16 k
    int brow = tid >> 2, bkq = (tid & 3) * 4;   // B copy: 64 rows x 16 k
    const float* aptr = A + (size_t)(bm + arow) * K + akq;
    const float* bptr = B + (size_t)(bn + brow) * K + bkq;
    int bsz = ((bn + brow) < N) ? 16 : 0;

    int nk = K / BK;

    // prologue: tile 0 -> buf 0
    {
        uint32_t da0 = smem_u32(&As[0][arow][akq]);
        uint32_t da1 = smem_u32(&As[0][arow][akq + 8]);
        uint32_t db  = smem_u32(&Bs[0][brow][bkq]);
        asm volatile("cp.async.cg.shared.global [%0], [%1], 16;" :: "r"(da0), "l"(aptr));
        asm volatile("cp.async.cg.shared.global [%0], [%1], 16;" :: "r"(da1), "l"(aptr + 8));
        asm volatile("cp.async.cg.shared.global [%0], [%1], 16, %2;" :: "r"(db), "l"(bptr), "r"(bsz));
        asm volatile("cp.async.commit_group;");
    }

    for (int i = 0; i < nk; i++) {
        int buf = i & 1;
        if (i + 1 < nk) {
            int k0 = (i + 1) * BK;
            uint32_t da0 = smem_u32(&As[buf ^ 1][arow][akq]);
            uint32_t da1 = smem_u32(&As[buf ^ 1][arow][akq + 8]);
            uint32_t db  = smem_u32(&Bs[buf ^ 1][brow][bkq]);
            asm volatile("cp.async.cg.shared.global [%0], [%1], 16;" :: "r"(da0), "l"(aptr + k0));
            asm volatile("cp.async.cg.shared.global [%0], [%1], 16;" :: "r"(da1), "l"(aptr + k0 + 8));
            asm volatile("cp.async.cg.shared.global [%0], [%1], 16, %2;" :: "r"(db), "l"(bptr + k0), "r"(bsz));
            asm volatile("cp.async.commit_group;");
            asm volatile("cp.async.wait_group 1;");
        } else {
            asm volatile("cp.async.wait_group 0;");
        }
        __syncthreads();

        #pragma unroll
        for (int c = 0; c < 2; c++) {
            int kb = c * 8;
            uint32_t afr[2][4], bfr[4][2];
            #pragma unroll
            for (int mt = 0; mt < 2; mt++) {
                int r = m0 + mt * 16 + gid;
                afr[mt][0] = __float_as_uint(As[buf][r    ][kb + tig]);
                afr[mt][1] = __float_as_uint(As[buf][r + 8][kb + tig]);
                afr[mt][2] = __float_as_uint(As[buf][r    ][kb + tig + 4]);
                afr[mt][3] = __float_as_uint(As[buf][r + 8][kb + tig + 4]);
            }
            #pragma unroll
            for (int nt = 0; nt < 4; nt++) {
                int cn = n0 + nt * 8 + gid;
                bfr[nt][0] = __float_as_uint(Bs[buf][cn][kb + tig]);
                bfr[nt][1] = __float_as_uint(Bs[buf][cn][kb + tig + 4]);
            }
            #pragma unroll
            for (int mt = 0; mt < 2; mt++)
                #pragma unroll
                for (int nt = 0; nt < 4; nt++)
                    mma_tf32(acc[mt][nt], afr[mt], bfr[nt]);
        }
        __syncthreads();
    }

    // epilogue
    #pragma unroll
    for (int mt = 0; mt < 2; mt++) {
        int r = bm + m0 + mt * 16 + gid;
        #pragma unroll
        for (int nt = 0; nt < 4; nt++) {
            int nb = bn + n0 + nt * 8;
            if (nb < N) {
                int cn = nb + tig * 2;
                float2 v0 = make_float2(acc[mt][nt][0], acc[mt][nt][1]);
                float2 v1 = make_float2(acc[mt][nt][2], acc[mt][nt][3]);
                *(float2*)&C[(size_t)r * N + cn]       = v0;
                *(float2*)&C[(size_t)(r + 8) * N + cn] = v1;
            }
        }
    }
}

// ---------------- causal depthwise conv (k=4) + silu ----------------
__global__ void __launch_bounds__(256) conv_silu_kernel(
    const float* __restrict__ cw, const float* __restrict__ cb)
{
    int n = blockIdx.x, t0 = blockIdx.y * 64, d = threadIdx.x;
    float w0 = cw[d * 4 + 0], w1 = cw[d * 4 + 1], w2 = cw[d * 4 + 2], w3 = cw[d * 4 + 3];
    float bias = cb[d];
    const float* xp = g_xz + (size_t)n * TT * 2 * DII + d;
    float* up = g_u + (size_t)n * TT * DII + d;
    float x0 = (t0 - 3 >= 0) ? xp[(size_t)(t0 - 3) * 2 * DII] : 0.f;
    float x1 = (t0 - 2 >= 0) ? xp[(size_t)(t0 - 2) * 2 * DII] : 0.f;
    float x2 = (t0 - 1 >= 0) ? xp[(size_t)(t0 - 1) * 2 * DII] : 0.f;
    for (int tt = 0; tt < 64; tt += 4) {
        float a0 = xp[(size_t)(t0 + tt + 0) * 2 * DII];
        float a1 = xp[(size_t)(t0 + tt + 1) * 2 * DII];
        float a2 = xp[(size_t)(t0 + tt + 2) * 2 * DII];
        float a3 = xp[(size_t)(t0 + tt + 3) * 2 * DII];
        float s0 = w0 * x0 + w1 * x1 + w2 * x2 + w3 * a0 + bias;
        float s1 = w0 * x1 + w1 * x2 + w2 * a0 + w3 * a1 + bias;
        float s2 = w0 * x2 + w1 * a0 + w2 * a1 + w3 * a2 + bias;
        float s3 = w0 * a0 + w1 * a1 + w2 * a2 + w3 * a3 + bias;
        up[(size_t)(t0 + tt + 0) * DII] = s0 / (1.f + __expf(-s0));
        up[(size_t)(t0 + tt + 1) * DII] = s1 / (1.f + __expf(-s1));
        up[(size_t)(t0 + tt + 2) * DII] = s2 / (1.f + __expf(-s2));
        up[(size_t)(t0 + tt + 3) * DII] = s3 / (1.f + __expf(-s3));
        x0 = a1; x1 = a2; x2 = a3;
    }
}

// ---------------- selective scan (fused dt-proj + softplus + gating) ----------------
__global__ void __launch_bounds__(128) scan_kernel(
    const float* __restrict__ dtw, const float* __restrict__ dtb,
    const float* __restrict__ alog, const float* __restrict__ Dv)
{
    int n = blockIdx.x;
    int tid = threadIdx.x;
    int d = blockIdx.y * 128 + tid;

    float A[DSS], hst[DSS], wdt[DTRR];
    bool fastA = true;
    #pragma unroll
    for (int s = 0; s < DSS; s++) {
        A[s] = -__expf(alog[d * DSS + s]);
        hst[s] = 0.f;
        fastA = fastA && (A[s] == -(float)(s + 1));
    }
    #pragma unroll
    for (int j = 0; j < DTRR; j++) wdt[j] = dtw[d * DTRR + j];
    float dtbd = dtb[d], Dd = Dv[d];

    __shared__ float sx[3][48];

    const size_t base_u = (size_t)n * TT * DII + d;
    const size_t base_z = (size_t)n * TT * 2 * DII + DII + d;
    const size_t base_x = (size_t)n * TT * 40;

    float u_a = g_u[base_u],        z_a = g_xz[base_z];
    float u_b = g_u[base_u + DII],  z_b = g_xz[base_z + 2 * DII];
    if (tid < 40) {
        sx[0][tid] = g_xdbl[base_x + tid];
        sx[1][tid] = g_xdbl[base_x + 40 + tid];
    }
    __syncthreads();

    for (int t = 0; t < TT; t++) {
        float u_n = 0.f, z_n = 0.f;
        if (t + 2 < TT) {
            u_n = g_u[base_u + (size_t)(t + 2) * DII];
            z_n = g_xz[base_z + (size_t)(t + 2) * 2 * DII];
            if (tid < 40)
                sx[(t + 2) % 3][tid] = g_xdbl[base_x + (size_t)(t + 2) * 40 + tid];
        }
        const float* sc = sx[t % 3];
        float dtv = dtbd;
        #pragma unroll
        for (int j = 0; j < DTRR; j++) dtv += sc[j] * wdt[j];
        float delta = (dtv > 15.f) ? dtv : log1pf(__expf(dtv));
        float du = delta * u_a;
        float y = 0.f;
        if (fastA) {
            // A[s] == -(s+1): exp(delta*A[s]) = p^(s+1), p = exp(-delta)
            float p = __expf(-delta);
            float pw = 1.f;
            #pragma unroll
            for (int s = 0; s < DSS; s++) {
                pw *= p;
                hst[s] = pw * hst[s] + du * sc[8 + s];
                y += hst[s] * sc[24 + s];
            }
        } else {
            #pragma unroll
            for (int s = 0; s < DSS; s++) {
                float e = __expf(delta * A[s]);
                hst[s] = e * hst[s] + du * sc[8 + s];
                y += hst[s] * sc[24 + s];
            }
        }
        y += u_a * Dd;
        float sz = z_a / (1.f + __expf(-z_a));
        g_ym[base_u + (size_t)t * DII] = y * sz;
        u_a = u_b; z_a = z_b; u_b = u_n; z_b = z_n;
        __syncthreads();
    }
}

// ---------------- residual add + layernorm (in place on g_h) ----------------
__global__ void __launch_bounds__(128) res_ln_kernel(
    const float* __restrict__ nw, const float* __restrict__ nb)
{
    size_t r = blockIdx.x;
    int d = threadIdx.x;
    float v = g_h[r * DMM + d] + g_yo[r * DMM + d];
    float mu, var;
    row_stats128(v, mu, var);
    g_h[r * DMM + d] = (v - mu) * rsqrtf(var + LNEPS) * nw[d] + nb[d];
}

// ---------------- final layernorm + mean over T ----------------
__global__ void __launch_bounds__(128) final_partial_kernel(
    const float* __restrict__ w, const float* __restrict__ b)
{
    int n = blockIdx.x, t0 = blockIdx.y * 64, d = threadIdx.x;
    float wd = w[d], bd = b[d], acc = 0.f;
    for (int tt = 0; tt < 64; tt++) {
        float v = g_h[(size_t)(n * TT + t0 + tt) * DMM + d];
        float mu, var;
        row_stats128(v, mu, var);
        acc += (v - mu) * rsqrtf(var + LNEPS) * wd + bd;
    }
    g_part[(size_t)(n * 4 + blockIdx.y) * DMM + d] = acc;
}

__global__ void __launch_bounds__(128) final_combine_kernel(float* __restrict__ out)
{
    int n = blockIdx.x, d = threadIdx.x;
    float s = g_part[(size_t)(n * 4 + 0) * DMM + d]
            + g_part[(size_t)(n * 4 + 1) * DMM + d]
            + g_part[(size_t)(n * 4 + 2) * DMM + d]
            + g_part[(size_t)(n * 4 + 3) * DMM + d];
    out[(size_t)n * DMM + d] = s * (1.0f / TT);
}

// ---------------- launch ----------------
extern "C" void kernel_launch(void* const* d_in, const int* in_sizes, int n_in,
                              void* d_out, int out_size)
{
    (void)in_sizes; (void)n_in; (void)out_size;
    const float* x     = (const float*)d_in[0];
    const float* inp_w = (const float*)d_in[1];
    const float* inp_b = (const float*)d_in[2];
    const float* ipw   = (const float*)d_in[3];
    const float* cw    = (const float*)d_in[4];
    const float* cb    = (const float*)d_in[5];
    const float* xpw   = (const float*)d_in[6];
    const float* dtw   = (const float*)d_in[7];
    const float* dtb   = (const float*)d_in[8];
    const float* alog  = (const float*)d_in[9];
    const float* Dv    = (const float*)d_in[10];
    const float* opw   = (const float*)d_in[11];
    const float* nw    = (const float*)d_in[12];
    const float* nb    = (const float*)d_in[13];
    const float* onw   = (const float*)d_in[14];
    const float* onb   = (const float*)d_in[15];
    float* out = (float*)d_out;

    float *ph, *pxz, *pu, *pxd, *pym, *pyo;
    cudaGetSymbolAddress((void**)&ph,  g_h);
    cudaGetSymbolAddress((void**)&pxz, g_xz);
    cudaGetSymbolAddress((void**)&pu,  g_u);
    cudaGetSymbolAddress((void**)&pxd, g_xdbl);
    cudaGetSymbolAddress((void**)&pym, g_ym);
    cudaGetSymbolAddress((void**)&pyo, g_yo);

    input_proj_kernel<<<dim3(NSEQ, 4), 128>>>(x, inp_w, inp_b);

    for (int l = 0; l < 2; l++) {
        // xz = h @ in_proj_w^T   [16384,512], K=128
        mma_gemm_kernel<<<dim3(ROWS / 128, 8), 256>>>(
            ph, ipw + (size_t)l * 2 * DII * DMM, pxz, ROWS, 2 * DII, DMM);
        // u = silu(conv(xi)+b)
        conv_silu_kernel<<<dim3(NSEQ, 4), 256>>>(cw + (size_t)l * DII * 4, cb + (size_t)l * DII);
        // x_dbl = u @ x_proj_w^T  [16384,40], K=256
        mma_gemm_kernel<<<dim3(ROWS / 128, 1), 256>>>(
            pu, xpw + (size_t)l * 40 * DII, pxd, ROWS, 40, DII);
        // scan
        scan_kernel<<<dim3(NSEQ, 2), 128>>>(dtw + (size_t)l * DII * DTRR, dtb + (size_t)l * DII,
                                            alog + (size_t)l * DII * DSS, Dv + (size_t)l * DII);
        // yo = ym @ out_proj_w^T  [16384,128], K=256
        mma_gemm_kernel<<<dim3(ROWS / 128, 2), 256>>>(
            pym, opw + (size_t)l * DMM * DII, pyo, ROWS, DMM, DII);
        // h = LN(h + yo)
        res_ln_kernel<<<ROWS, 128>>>(nw + (size_t)l * DMM, nb + (size_t)l * DMM);
    }

    final_partial_kernel<<<dim3(NSEQ, 4), 128>>>(onw, onb);
    final_combine_kernel<<<NSEQ, 128>>>(out);
}

// round 3
// speedup vs baseline: 1.7340x; 1.2772x over previous
#include <cuda_runtime.h>
#include <math.h>
#include <stdint.h>

#define NSEQ 64
#define TT   256
#define FF   64
#define DMM  128
#define DII  256
#define DSS  16
#define DTRR 8
#define ROWS (NSEQ*TT)
#define LNEPS 1e-5f

// ---------------- scratch ----------------
__device__ float g_h   [ROWS*DMM];
__device__ float g_xz  [ROWS*2*DII];
__device__ float g_u   [ROWS*DII];
__device__ float g_xdbl[ROWS*40];
__device__ float g_ym  [ROWS*DII];
__device__ float g_part[NSEQ*4*DMM];

// ---------------- helpers ----------------
__device__ __forceinline__ uint32_t smem_u32(const void* p) {
    return (uint32_t)__cvta_generic_to_shared(p);
}
__device__ __forceinline__ void mma_tf32(float* c, const uint32_t* a, const uint32_t* b) {
    asm volatile(
        "mma.sync.aligned.m16n8k8.row.col.f32.tf32.tf32.f32 "
        "{%0,%1,%2,%3}, {%4,%5,%6,%7}, {%8,%9}, {%0,%1,%2,%3};"
        : "+f"(c[0]), "+f"(c[1]), "+f"(c[2]), "+f"(c[3])
        : "r"(a[0]), "r"(a[1]), "r"(a[2]), "r"(a[3]), "r"(b[0]), "r"(b[1]));
}
__device__ __forceinline__ void row_stats128(float v, float& mu, float& var) {
    float s = v, q = v * v;
    #pragma unroll
    for (int o = 16; o; o >>= 1) {
        s += __shfl_down_sync(0xffffffffu, s, o);
        q += __shfl_down_sync(0xffffffffu, q, o);
    }
    __shared__ float ss[4], sq[4];
    int w = threadIdx.x >> 5;
    if ((threadIdx.x & 31) == 0) { ss[w] = s; sq[w] = q; }
    __syncthreads();
    s = ss[0] + ss[1] + ss[2] + ss[3];
    q = sq[0] + sq[1] + sq[2] + sq[3];
    __syncthreads();
    mu  = s * (1.0f / DMM);
    var = q * (1.0f / DMM) - mu * mu;
}

// ---------------- input projection ----------------
__global__ void __launch_bounds__(128) input_proj_kernel(
    const float* __restrict__ x, const float* __restrict__ w, const float* __restrict__ b)
{
    int n = blockIdx.x, t0 = blockIdx.y * 64, d = threadIdx.x;
    __shared__ float xsT[FF][64];
    float wreg[FF];
    #pragma unroll
    for (int f = 0; f < FF; f++) wreg[f] = w[d * FF + f];
    float bias = b[d];
    for (int idx = threadIdx.x; idx < FF * 64; idx += 128) {
        int f = idx >> 6, tt = idx & 63;
        xsT[f][tt] = x[(size_t)n * FF * TT + (size_t)f * TT + t0 + tt];
    }
    __syncthreads();
    for (int tt = 0; tt < 64; tt++) {
        float acc = bias;
        #pragma unroll
        for (int f = 0; f < FF; f++) acc += wreg[f] * xsT[f][tt];
        g_h[(size_t)(n * TT + t0 + tt) * DMM + d] = acc;
    }
}

// ---------------- tf32 GEMM: C[M,N]=A[M,K]@B[N,K]^T. BM=BN=64, 128 thr, 4 warps ----------------
__global__ void __launch_bounds__(128) mma_gemm_kernel(
    const float* __restrict__ A, const float* __restrict__ B, float* __restrict__ C,
    int M, int N, int K)
{
    const int BM = 64, BN = 64, BK = 16;
    __shared__ float As[2][BM][BK + 4];
    __shared__ float Bs[2][BN][BK + 4];

    int tid  = threadIdx.x;
    int bm   = blockIdx.x * BM, bn = blockIdx.y * BN;
    int warp = tid >> 5, lane = tid & 31;
    int gid  = lane >> 2, tig = lane & 3;
    int m0   = (warp & 1) * 32;
    int n0   = (warp >> 1) * 32;

    float acc[2][4][4];
    #pragma unroll
    for (int i = 0; i < 2; i++)
        #pragma unroll
        for (int j = 0; j < 4; j++)
            #pragma unroll
            for (int k = 0; k < 4; k++) acc[i][j][k] = 0.f;

    int arow = tid >> 1, akq = (tid & 1) * 8;
    const float* aptr = A + (size_t)(bm + arow) * K + akq;
    const float* bptr = B + (size_t)(bn + arow) * K + akq;
    int bsz = ((bn + arow) < N) ? 16 : 0;
    int nk = K / BK;

    {
        uint32_t da0 = smem_u32(&As[0][arow][akq]);
        uint32_t da1 = smem_u32(&As[0][arow][akq + 4]);
        uint32_t db0 = smem_u32(&Bs[0][arow][akq]);
        uint32_t db1 = smem_u32(&Bs[0][arow][akq + 4]);
        asm volatile("cp.async.cg.shared.global [%0], [%1], 16;" :: "r"(da0), "l"(aptr));
        asm volatile("cp.async.cg.shared.global [%0], [%1], 16;" :: "r"(da1), "l"(aptr + 4));
        asm volatile("cp.async.cg.shared.global [%0], [%1], 16, %2;" :: "r"(db0), "l"(bptr), "r"(bsz));
        asm volatile("cp.async.cg.shared.global [%0], [%1], 16, %2;" :: "r"(db1), "l"(bptr + 4), "r"(bsz));
        asm volatile("cp.async.commit_group;");
    }

    for (int i = 0; i < nk; i++) {
        int buf = i & 1;
        if (i + 1 < nk) {
            int k0 = (i + 1) * BK;
            uint32_t da0 = smem_u32(&As[buf ^ 1][arow][akq]);
            uint32_t da1 = smem_u32(&As[buf ^ 1][arow][akq + 4]);
            uint32_t db0 = smem_u32(&Bs[buf ^ 1][arow][akq]);
            uint32_t db1 = smem_u32(&Bs[buf ^ 1][arow][akq + 4]);
            asm volatile("cp.async.cg.shared.global [%0], [%1], 16;" :: "r"(da0), "l"(aptr + k0));
            asm volatile("cp.async.cg.shared.global [%0], [%1], 16;" :: "r"(da1), "l"(aptr + k0 + 4));
            asm volatile("cp.async.cg.shared.global [%0], [%1], 16, %2;" :: "r"(db0), "l"(bptr + k0), "r"(bsz));
            asm volatile("cp.async.cg.shared.global [%0], [%1], 16, %2;" :: "r"(db1), "l"(bptr + k0 + 4), "r"(bsz));
            asm volatile("cp.async.commit_group;");
            asm volatile("cp.async.wait_group 1;");
        } else {
            asm volatile("cp.async.wait_group 0;");
        }
        __syncthreads();

        #pragma unroll
        for (int c = 0; c < 2; c++) {
            int kb = c * 8;
            uint32_t afr[2][4], bfr[4][2];
            #pragma unroll
            for (int mt = 0; mt < 2; mt++) {
                int r = m0 + mt * 16 + gid;
                afr[mt][0] = __float_as_uint(As[buf][r    ][kb + tig]);
                afr[mt][1] = __float_as_uint(As[buf][r + 8][kb + tig]);
                afr[mt][2] = __float_as_uint(As[buf][r    ][kb + tig + 4]);
                afr[mt][3] = __float_as_uint(As[buf][r + 8][kb + tig + 4]);
            }
            #pragma unroll
            for (int nt = 0; nt < 4; nt++) {
                int cn = n0 + nt * 8 + gid;
                bfr[nt][0] = __float_as_uint(Bs[buf][cn][kb + tig]);
                bfr[nt][1] = __float_as_uint(Bs[buf][cn][kb + tig + 4]);
            }
            #pragma unroll
            for (int mt = 0; mt < 2; mt++)
                #pragma unroll
                for (int nt = 0; nt < 4; nt++)
                    mma_tf32(acc[mt][nt], afr[mt], bfr[nt]);
        }
        __syncthreads();
    }

    #pragma unroll
    for (int mt = 0; mt < 2; mt++) {
        int r = bm + m0 + mt * 16 + gid;
        #pragma unroll
        for (int nt = 0; nt < 4; nt++) {
            int nb = bn + n0 + nt * 8;
            if (nb < N) {
                int cn = nb + tig * 2;
                *(float2*)&C[(size_t)r * N + cn]       = make_float2(acc[mt][nt][0], acc[mt][nt][1]);
                *(float2*)&C[(size_t)(r + 8) * N + cn] = make_float2(acc[mt][nt][2], acc[mt][nt][3]);
            }
        }
    }
}

// ---------------- fused out_proj GEMM + residual + LayerNorm ----------------
// C[64,128] tile = ym @ opw^T; h = LN(h + C). BM=64, BN=128, BK=16, 256 thr.
__global__ void __launch_bounds__(256) outproj_ln_kernel(
    const float* __restrict__ A, const float* __restrict__ B,
    const float* __restrict__ nw, const float* __restrict__ nb)
{
    const int BM = 64, BK = 16, K = DII;
    __shared__ float As[2][BM][BK + 4];
    __shared__ float Bs[2][DMM][BK + 4];
    __shared__ float Cs[BM][DMM + 4];

    int tid  = threadIdx.x;
    int bm   = blockIdx.x * BM;
    int warp = tid >> 5, lane = tid & 31;
    int gid  = lane >> 2, tig = lane & 3;
    int m0   = (warp & 1) * 32;
    int n0   = (warp >> 1) * 32;

    float acc[2][4][4];
    #pragma unroll
    for (int i = 0; i < 2; i++)
        #pragma unroll
        for (int j = 0; j < 4; j++)
            #pragma unroll
            for (int k = 0; k < 4; k++) acc[i][j][k] = 0.f;

    int arow = tid >> 2, akq = (tid & 3) * 4;        // 64 rows x 16: 1 f4/thread
    int brow = tid >> 1, bkq = (tid & 1) * 8;        // 128 rows x 16: 2 f4/thread
    const float* aptr = A + (size_t)(bm + arow) * K + akq;
    const float* bptr = B + (size_t)brow * K + bkq;
    const int nk = K / BK;

    {
        uint32_t da  = smem_u32(&As[0][arow][akq]);
        uint32_t db0 = smem_u32(&Bs[0][brow][bkq]);
        uint32_t db1 = smem_u32(&Bs[0][brow][bkq + 4]);
        asm volatile("cp.async.cg.shared.global [%0], [%1], 16;" :: "r"(da),  "l"(aptr));
        asm volatile("cp.async.cg.shared.global [%0], [%1], 16;" :: "r"(db0), "l"(bptr));
        asm volatile("cp.async.cg.shared.global [%0], [%1], 16;" :: "r"(db1), "l"(bptr + 4));
        asm volatile("cp.async.commit_group;");
    }

    for (int i = 0; i < nk; i++) {
        int buf = i & 1;
        if (i + 1 < nk) {
            int k0 = (i + 1) * BK;
            uint32_t da  = smem_u32(&As[buf ^ 1][arow][akq]);
            uint32_t db0 = smem_u32(&Bs[buf ^ 1][brow][bkq]);
            uint32_t db1 = smem_u32(&Bs[buf ^ 1][brow][bkq + 4]);
            asm volatile("cp.async.cg.shared.global [%0], [%1], 16;" :: "r"(da),  "l"(aptr + k0));
            asm volatile("cp.async.cg.shared.global [%0], [%1], 16;" :: "r"(db0), "l"(bptr + k0));
            asm volatile("cp.async.cg.shared.global [%0], [%1], 16;" :: "r"(db1), "l"(bptr + k0 + 4));
            asm volatile("cp.async.commit_group;");
            asm volatile("cp.async.wait_group 1;");
        } else {
            asm volatile("cp.async.wait_group 0;");
        }
        __syncthreads();

        #pragma unroll
        for (int c = 0; c < 2; c++) {
            int kb = c * 8;
            uint32_t afr[2][4], bfr[4][2];
            #pragma unroll
            for (int mt = 0; mt < 2; mt++) {
                int r = m0 + mt * 16 + gid;
                afr[mt][0] = __float_as_uint(As[buf][r    ][kb + tig]);
                afr[mt][1] = __float_as_uint(As[buf][r + 8][kb + tig]);
                afr[mt][2] = __float_as_uint(As[buf][r    ][kb + tig + 4]);
                afr[mt][3] = __float_as_uint(As[buf][r + 8][kb + tig + 4]);
            }
            #pragma unroll
            for (int nt = 0; nt < 4; nt++) {
                int cn = n0 + nt * 8 + gid;
                bfr[nt][0] = __float_as_uint(Bs[buf][cn][kb + tig]);
                bfr[nt][1] = __float_as_uint(Bs[buf][cn][kb + tig + 4]);
            }
            #pragma unroll
            for (int mt = 0; mt < 2; mt++)
                #pragma unroll
                for (int nt = 0; nt < 4; nt++)
                    mma_tf32(acc[mt][nt], afr[mt], bfr[nt]);
        }
        __syncthreads();
    }

    // stage C tile in smem
    #pragma unroll
    for (int mt = 0; mt < 2; mt++) {
        int r = m0 + mt * 16 + gid;
        #pragma unroll
        for (int nt = 0; nt < 4; nt++) {
            int cn = n0 + nt * 8 + tig * 2;
            *(float2*)&Cs[r    ][cn] = make_float2(acc[mt][nt][0], acc[mt][nt][1]);
            *(float2*)&Cs[r + 8][cn] = make_float2(acc[mt][nt][2], acc[mt][nt][3]);
        }
    }
    __syncthreads();

    // residual + LN: warp w handles rows w*8 .. w*8+7
    float w0 = nw[lane], w1 = nw[lane + 32], w2 = nw[lane + 64], w3 = nw[lane + 96];
    float b0 = nb[lane], b1 = nb[lane + 32], b2 = nb[lane + 64], b3 = nb[lane + 96];
    for (int rr = warp * 8; rr < warp * 8 + 8; rr++) {
        size_t gr = (size_t)(bm + rr) * DMM;
        float v0 = Cs[rr][lane]      + g_h[gr + lane];
        float v1 = Cs[rr][lane + 32] + g_h[gr + lane + 32];
        float v2 = Cs[rr][lane + 64] + g_h[gr + lane + 64];
        float v3 = Cs[rr][lane + 96] + g_h[gr + lane + 96];
        float s = v0 + v1 + v2 + v3;
        float q = v0 * v0 + v1 * v1 + v2 * v2 + v3 * v3;
        #pragma unroll
        for (int o = 16; o; o >>= 1) {
            s += __shfl_xor_sync(0xffffffffu, s, o);
            q += __shfl_xor_sync(0xffffffffu, q, o);
        }
        float mu = s * (1.0f / DMM);
        float var = q * (1.0f / DMM) - mu * mu;
        float rs = rsqrtf(var + LNEPS);
        g_h[gr + lane]      = (v0 - mu) * rs * w0 + b0;
        g_h[gr + lane + 32] = (v1 - mu) * rs * w1 + b1;
        g_h[gr + lane + 64] = (v2 - mu) * rs * w2 + b2;
        g_h[gr + lane + 96] = (v3 - mu) * rs * w3 + b3;
    }
}

// ---------------- causal depthwise conv (k=4) + silu ----------------
__global__ void __launch_bounds__(256) conv_silu_kernel(
    const float* __restrict__ cw, const float* __restrict__ cb)
{
    int n = blockIdx.x, t0 = blockIdx.y * 64, d = threadIdx.x;
    float w0 = cw[d * 4 + 0], w1 = cw[d * 4 + 1], w2 = cw[d * 4 + 2], w3 = cw[d * 4 + 3];
    float bias = cb[d];
    const float* xp = g_xz + (size_t)n * TT * 2 * DII + d;
    float* up = g_u + (size_t)n * TT * DII + d;
    float x0 = (t0 - 3 >= 0) ? xp[(size_t)(t0 - 3) * 2 * DII] : 0.f;
    float x1 = (t0 - 2 >= 0) ? xp[(size_t)(t0 - 2) * 2 * DII] : 0.f;
    float x2 = (t0 - 1 >= 0) ? xp[(size_t)(t0 - 1) * 2 * DII] : 0.f;
    for (int tt = 0; tt < 64; tt += 4) {
        float a0 = xp[(size_t)(t0 + tt + 0) * 2 * DII];
        float a1 = xp[(size_t)(t0 + tt + 1) * 2 * DII];
        float a2 = xp[(size_t)(t0 + tt + 2) * 2 * DII];
        float a3 = xp[(size_t)(t0 + tt + 3) * 2 * DII];
        float s0 = w0 * x0 + w1 * x1 + w2 * x2 + w3 * a0 + bias;
        float s1 = w0 * x1 + w1 * x2 + w2 * a0 + w3 * a1 + bias;
        float s2 = w0 * x2 + w1 * a0 + w2 * a1 + w3 * a2 + bias;
        float s3 = w0 * a0 + w1 * a1 + w2 * a2 + w3 * a3 + bias;
        up[(size_t)(t0 + tt + 0) * DII] = s0 / (1.f + __expf(-s0));
        up[(size_t)(t0 + tt + 1) * DII] = s1 / (1.f + __expf(-s1));
        up[(size_t)(t0 + tt + 2) * DII] = s2 / (1.f + __expf(-s2));
        up[(size_t)(t0 + tt + 3) * DII] = s3 / (1.f + __expf(-s3));
        x0 = a1; x1 = a2; x2 = a3;
    }
}

// ---------------- selective scan: all x_dbl in smem, no in-loop barriers ----------------
__global__ void __launch_bounds__(128) scan_kernel(
    const float* __restrict__ dtw, const float* __restrict__ dtb,
    const float* __restrict__ alog, const float* __restrict__ Dv)
{
    int n = blockIdx.x;
    int tid = threadIdx.x;
    int d = blockIdx.y * 128 + tid;

    __shared__ float4 sx4[TT * 10];          // 256 t x 40 floats = 40KB
    {
        const float4* src = (const float4*)(g_xdbl + (size_t)n * TT * 40);
        #pragma unroll
        for (int i = 0; i < 20; i++) {
            int idx = tid + i * 128;
            uint32_t dst = smem_u32(&sx4[idx]);
            asm volatile("cp.async.cg.shared.global [%0], [%1], 16;" :: "r"(dst), "l"(src + idx));
        }
        asm volatile("cp.async.commit_group;");
    }

    float A[DSS], hst[DSS], wdt[DTRR];
    bool fastA = true;
    #pragma unroll
    for (int s = 0; s < DSS; s++) {
        A[s] = -__expf(alog[d * DSS + s]);
        hst[s] = 0.f;
        fastA = fastA && (A[s] == -(float)(s + 1));
    }
    #pragma unroll
    for (int j = 0; j < DTRR; j++) wdt[j] = dtw[d * DTRR + j];
    float dtbd = dtb[d], Dd = Dv[d];

    const size_t base_u = (size_t)n * TT * DII + d;
    const size_t base_z = (size_t)n * TT * 2 * DII + DII + d;

    float u_a = g_u[base_u],        z_a = g_xz[base_z];
    float u_b = g_u[base_u + DII],  z_b = g_xz[base_z + 2 * DII];

    asm volatile("cp.async.wait_group 0;");
    __syncthreads();

    const float* sxa = (const float*)sx4;
    for (int t = 0; t < TT; t++) {
        float u_n = 0.f, z_n = 0.f;
        if (t + 2 < TT) {
            u_n = g_u[base_u + (size_t)(t + 2) * DII];
            z_n = g_xz[base_z + (size_t)(t + 2) * 2 * DII];
        }
        const float4* sc4 = (const float4*)(sxa + t * 40);
        float4 d0 = sc4[0], d1 = sc4[1];
        float4 Bv0 = sc4[2], Bv1 = sc4[3], Bv2 = sc4[4], Bv3 = sc4[5];
        float4 Cv0 = sc4[6], Cv1 = sc4[7], Cv2 = sc4[8], Cv3 = sc4[9];
        float Bf[16] = {Bv0.x,Bv0.y,Bv0.z,Bv0.w, Bv1.x,Bv1.y,Bv1.z,Bv1.w,
                        Bv2.x,Bv2.y,Bv2.z,Bv2.w, Bv3.x,Bv3.y,Bv3.z,Bv3.w};
        float Cf[16] = {Cv0.x,Cv0.y,Cv0.z,Cv0.w, Cv1.x,Cv1.y,Cv1.z,Cv1.w,
                        Cv2.x,Cv2.y,Cv2.z,Cv2.w, Cv3.x,Cv3.y,Cv3.z,Cv3.w};
        float dtv = dtbd;
        dtv += d0.x * wdt[0]; dtv += d0.y * wdt[1]; dtv += d0.z * wdt[2]; dtv += d0.w * wdt[3];
        dtv += d1.x * wdt[4]; dtv += d1.y * wdt[5]; dtv += d1.z * wdt[6]; dtv += d1.w * wdt[7];
        float delta = (dtv > 15.f) ? dtv : log1pf(__expf(dtv));
        float du = delta * u_a;
        float y = 0.f;
        if (fastA) {
            float p = __expf(-delta);
            float pw = 1.f;
            #pragma unroll
            for (int s = 0; s < DSS; s++) {
                pw *= p;
                hst[s] = pw * hst[s] + du * Bf[s];
                y += hst[s] * Cf[s];
            }
        } else {
            #pragma unroll
            for (int s = 0; s < DSS; s++) {
                float e = __expf(delta * A[s]);
                hst[s] = e * hst[s] + du * Bf[s];
                y += hst[s] * Cf[s];
            }
        }
        y += u_a * Dd;
        float sz = z_a / (1.f + __expf(-z_a));
        g_ym[base_u + (size_t)t * DII] = y * sz;
        u_a = u_b; z_a = z_b; u_b = u_n; z_b = z_n;
    }
}

// ---------------- final layernorm + mean over T ----------------
__global__ void __launch_bounds__(128) final_partial_kernel(
    const float* __restrict__ w, const float* __restrict__ b)
{
    int n = blockIdx.x, t0 = blockIdx.y * 64, d = threadIdx.x;
    float wd = w[d], bd = b[d], acc = 0.f;
    for (int tt = 0; tt < 64; tt++) {
        float v = g_h[(size_t)(n * TT + t0 + tt) * DMM + d];
        float mu, var;
        row_stats128(v, mu, var);
        acc += (v - mu) * rsqrtf(var + LNEPS) * wd + bd;
    }
    g_part[(size_t)(n * 4 + blockIdx.y) * DMM + d] = acc;
}

__global__ void __launch_bounds__(128) final_combine_kernel(float* __restrict__ out)
{
    int n = blockIdx.x, d = threadIdx.x;
    float s = g_part[(size_t)(n * 4 + 0) * DMM + d]
            + g_part[(size_t)(n * 4 + 1) * DMM + d]
            + g_part[(size_t)(n * 4 + 2) * DMM + d]
            + g_part[(size_t)(n * 4 + 3) * DMM + d];
    out[(size_t)n * DMM + d] = s * (1.0f / TT);
}

// ---------------- launch ----------------
extern "C" void kernel_launch(void* const* d_in, const int* in_sizes, int n_in,
                              void* d_out, int out_size)
{
    (void)in_sizes; (void)n_in; (void)out_size;
    const float* x     = (const float*)d_in[0];
    const float* inp_w = (const float*)d_in[1];
    const float* inp_b = (const float*)d_in[2];
    const float* ipw   = (const float*)d_in[3];
    const float* cw    = (const float*)d_in[4];
    const float* cb    = (const float*)d_in[5];
    const float* xpw   = (const float*)d_in[6];
    const float* dtw   = (const float*)d_in[7];
    const float* dtb   = (const float*)d_in[8];
    const float* alog  = (const float*)d_in[9];
    const float* Dv    = (const float*)d_in[10];
    const float* opw   = (const float*)d_in[11];
    const float* nw    = (const float*)d_in[12];
    const float* nb    = (const float*)d_in[13];
    const float* onw   = (const float*)d_in[14];
    const float* onb   = (const float*)d_in[15];
    float* out = (float*)d_out;

    float *ph, *pxz, *pu, *pxd, *pym;
    cudaGetSymbolAddress((void**)&ph,  g_h);
    cudaGetSymbolAddress((void**)&pxz, g_xz);
    cudaGetSymbolAddress((void**)&pu,  g_u);
    cudaGetSymbolAddress((void**)&pxd, g_xdbl);
    cudaGetSymbolAddress((void**)&pym, g_ym);

    input_proj_kernel<<<dim3(NSEQ, 4), 128>>>(x, inp_w, inp_b);

    for (int l = 0; l < 2; l++) {
        // xz = h @ in_proj_w^T  [16384,512], K=128
        mma_gemm_kernel<<<dim3(ROWS / 64, 8), 128>>>(
            ph, ipw + (size_t)l * 2 * DII * DMM, pxz, ROWS, 2 * DII, DMM);
        // u = silu(conv(xi)+b)
        conv_silu_kernel<<<dim3(NSEQ, 4), 256>>>(cw + (size_t)l * DII * 4, cb + (size_t)l * DII);
        // x_dbl = u @ x_proj_w^T  [16384,40], K=256
        mma_gemm_kernel<<<dim3(ROWS / 64, 1), 128>>>(
            pu, xpw + (size_t)l * 40 * DII, pxd, ROWS, 40, DII);
        // fused scan
        scan_kernel<<<dim3(NSEQ, 2), 128>>>(dtw + (size_t)l * DII * DTRR, dtb + (size_t)l * DII,
                                            alog + (size_t)l * DII * DSS, Dv + (size_t)l * DII);
        // h = LN(h + ym @ out_proj_w^T)   fused
        outproj_ln_kernel<<<ROWS / 64, 256>>>(
            pym, opw + (size_t)l * DMM * DII, nw + (size_t)l * DMM, nb + (size_t)l * DMM);
    }

    final_partial_kernel<<<dim3(NSEQ, 4), 128>>>(onw, onb);
    final_combine_kernel<<<NSEQ, 128>>>(out);
}

// round 4
// speedup vs baseline: 2.0017x; 1.1544x over previous
#include <cuda_runtime.h>
#include <math.h>
#include <stdint.h>

#define NSEQ 64
#define TT   256
#define FF   64
#define DMM  128
#define DII  256
#define DSS  16
#define DTRR 8
#define ROWS (NSEQ*TT)
#define LNEPS 1e-5f

// ---------------- scratch ----------------
__device__ float g_h   [ROWS*DMM];
__device__ float g_xz  [ROWS*2*DII];
__device__ float g_u   [ROWS*DII];
__device__ float g_xdbl[ROWS*40];
__device__ float g_ym  [ROWS*DII];
__device__ float g_part[NSEQ*4*DMM];

// ---------------- helpers ----------------
__device__ __forceinline__ uint32_t smem_u32(const void* p) {
    return (uint32_t)__cvta_generic_to_shared(p);
}
__device__ __forceinline__ void mma_tf32(float* c, const uint32_t* a, const uint32_t* b) {
    asm volatile(
        "mma.sync.aligned.m16n8k8.row.col.f32.tf32.tf32.f32 "
        "{%0,%1,%2,%3}, {%4,%5,%6,%7}, {%8,%9}, {%0,%1,%2,%3};"
        : "+f"(c[0]), "+f"(c[1]), "+f"(c[2]), "+f"(c[3])
        : "r"(a[0]), "r"(a[1]), "r"(a[2]), "r"(a[3]), "r"(b[0]), "r"(b[1]));
}
__device__ __forceinline__ void row_stats128(float v, float& mu, float& var) {
    float s = v, q = v * v;
    #pragma unroll
    for (int o = 16; o; o >>= 1) {
        s += __shfl_down_sync(0xffffffffu, s, o);
        q += __shfl_down_sync(0xffffffffu, q, o);
    }
    __shared__ float ss[4], sq[4];
    int w = threadIdx.x >> 5;
    if ((threadIdx.x & 31) == 0) { ss[w] = s; sq[w] = q; }
    __syncthreads();
    s = ss[0] + ss[1] + ss[2] + ss[3];
    q = sq[0] + sq[1] + sq[2] + sq[3];
    __syncthreads();
    mu  = s * (1.0f / DMM);
    var = q * (1.0f / DMM) - mu * mu;
}

// ---------------- tensorized input projection ----------------
// h[n,t0+tt,d] = sum_f x[n,f,t0+tt]*w[d,f] + b[d]. 256 thr, 8 warps 32x32 tiles.
__global__ void __launch_bounds__(256) input_proj_mma(
    const float* __restrict__ x, const float* __restrict__ w, const float* __restrict__ bias)
{
    extern __shared__ float sm[];
    float* As = sm;              // [64 t][68]
    float* Bs = sm + 64 * 68;    // [128 d][68]
    int n = blockIdx.x, t0 = blockIdx.y * 64;
    int tid = threadIdx.x;

    // A: transpose x[n, f, t0:t0+64] -> As[t][f]
    #pragma unroll
    for (int p = 0; p < 4; p++) {
        int f = p * 16 + (tid >> 4), t4 = (tid & 15) * 4;
        float4 v = *(const float4*)(x + ((size_t)(n * FF + f)) * TT + t0 + t4);
        As[(t4 + 0) * 68 + f] = v.x;
        As[(t4 + 1) * 68 + f] = v.y;
        As[(t4 + 2) * 68 + f] = v.z;
        As[(t4 + 3) * 68 + f] = v.w;
    }
    // B: w[128][64] row copy
    #pragma unroll
    for (int i = 0; i < 8; i++) {
        int idx = tid + i * 256;
        int row = idx >> 4, c4 = (idx & 15) << 2;
        *(float4*)&Bs[row * 68 + c4] = *(const float4*)(w + row * 64 + c4);
    }
    __syncthreads();

    int warp = tid >> 5, lane = tid & 31;
    int gid = lane >> 2, tig = lane & 3;
    int m0 = (warp & 1) * 32, n0 = (warp >> 1) * 32;

    float acc[2][4][4];
    #pragma unroll
    for (int i = 0; i < 2; i++)
        #pragma unroll
        for (int j = 0; j < 4; j++)
            #pragma unroll
            for (int k = 0; k < 4; k++) acc[i][j][k] = 0.f;

    #pragma unroll
    for (int kb = 0; kb < 64; kb += 8) {
        uint32_t afr[2][4], bfr[4][2];
        #pragma unroll
        for (int mt = 0; mt < 2; mt++) {
            int r = m0 + mt * 16 + gid;
            afr[mt][0] = __float_as_uint(As[r * 68 + kb + tig]);
            afr[mt][1] = __float_as_uint(As[(r + 8) * 68 + kb + tig]);
            afr[mt][2] = __float_as_uint(As[r * 68 + kb + tig + 4]);
            afr[mt][3] = __float_as_uint(As[(r + 8) * 68 + kb + tig + 4]);
        }
        #pragma unroll
        for (int nt = 0; nt < 4; nt++) {
            int cn = n0 + nt * 8 + gid;
            bfr[nt][0] = __float_as_uint(Bs[cn * 68 + kb + tig]);
            bfr[nt][1] = __float_as_uint(Bs[cn * 68 + kb + tig + 4]);
        }
        #pragma unroll
        for (int mt = 0; mt < 2; mt++)
            #pragma unroll
            for (int nt = 0; nt < 4; nt++)
                mma_tf32(acc[mt][nt], afr[mt], bfr[nt]);
    }

    #pragma unroll
    for (int mt = 0; mt < 2; mt++) {
        int r = n * TT + t0 + m0 + mt * 16 + gid;
        #pragma unroll
        for (int nt = 0; nt < 4; nt++) {
            int cn = n0 + nt * 8 + tig * 2;
            float2 bv = *(const float2*)(bias + cn);
            *(float2*)&g_h[(size_t)r * DMM + cn] =
                make_float2(acc[mt][nt][0] + bv.x, acc[mt][nt][1] + bv.y);
            *(float2*)&g_h[(size_t)(r + 8) * DMM + cn] =
                make_float2(acc[mt][nt][2] + bv.x, acc[mt][nt][3] + bv.y);
        }
    }
}

// ---------------- tf32 GEMM (in_proj): C=A@B^T, BM=BN=64, BK=16, 128 thr, 1-sync loop --------
__global__ void __launch_bounds__(128) mma_gemm_kernel(
    const float* __restrict__ A, const float* __restrict__ B, float* __restrict__ C,
    int M, int N, int K)
{
    const int BK = 16;
    __shared__ float As[2][64][BK + 4];
    __shared__ float Bs[2][64][BK + 4];

    int tid  = threadIdx.x;
    int bm   = blockIdx.x * 64, bn = blockIdx.y * 64;
    int warp = tid >> 5, lane = tid & 31;
    int gid  = lane >> 2, tig = lane & 3;
    int m0   = (warp & 1) * 32;
    int n0   = (warp >> 1) * 32;

    float acc[2][4][4];
    #pragma unroll
    for (int i = 0; i < 2; i++)
        #pragma unroll
        for (int j = 0; j < 4; j++)
            #pragma unroll
            for (int k = 0; k < 4; k++) acc[i][j][k] = 0.f;

    int arow = tid >> 1, akq = (tid & 1) * 8;
    const float* aptr = A + (size_t)(bm + arow) * K + akq;
    const float* bptr = B + (size_t)(bn + arow) * K + akq;
    int bsz = ((bn + arow) < N) ? 16 : 0;
    int nk = K / BK;

    {
        uint32_t da0 = smem_u32(&As[0][arow][akq]);
        uint32_t da1 = smem_u32(&As[0][arow][akq + 4]);
        uint32_t db0 = smem_u32(&Bs[0][arow][akq]);
        uint32_t db1 = smem_u32(&Bs[0][arow][akq + 4]);
        asm volatile("cp.async.cg.shared.global [%0], [%1], 16;" :: "r"(da0), "l"(aptr));
        asm volatile("cp.async.cg.shared.global [%0], [%1], 16;" :: "r"(da1), "l"(aptr + 4));
        asm volatile("cp.async.cg.shared.global [%0], [%1], 16, %2;" :: "r"(db0), "l"(bptr), "r"(bsz));
        asm volatile("cp.async.cg.shared.global [%0], [%1], 16, %2;" :: "r"(db1), "l"(bptr + 4), "r"(bsz));
        asm volatile("cp.async.commit_group;");
    }

    for (int i = 0; i < nk; i++) {
        int buf = i & 1;
        asm volatile("cp.async.wait_group 0;");
        __syncthreads();
        if (i + 1 < nk) {
            int k0 = (i + 1) * BK;
            uint32_t da0 = smem_u32(&As[buf ^ 1][arow][akq]);
            uint32_t da1 = smem_u32(&As[buf ^ 1][arow][akq + 4]);
            uint32_t db0 = smem_u32(&Bs[buf ^ 1][arow][akq]);
            uint32_t db1 = smem_u32(&Bs[buf ^ 1][arow][akq + 4]);
            asm volatile("cp.async.cg.shared.global [%0], [%1], 16;" :: "r"(da0), "l"(aptr + k0));
            asm volatile("cp.async.cg.shared.global [%0], [%1], 16;" :: "r"(da1), "l"(aptr + k0 + 4));
            asm volatile("cp.async.cg.shared.global [%0], [%1], 16, %2;" :: "r"(db0), "l"(bptr + k0), "r"(bsz));
            asm volatile("cp.async.cg.shared.global [%0], [%1], 16, %2;" :: "r"(db1), "l"(bptr + k0 + 4), "r"(bsz));
            asm volatile("cp.async.commit_group;");
        }
        #pragma unroll
        for (int c = 0; c < 2; c++) {
            int kb = c * 8;
            uint32_t afr[2][4], bfr[4][2];
            #pragma unroll
            for (int mt = 0; mt < 2; mt++) {
                int r = m0 + mt * 16 + gid;
                afr[mt][0] = __float_as_uint(As[buf][r    ][kb + tig]);
                afr[mt][1] = __float_as_uint(As[buf][r + 8][kb + tig]);
                afr[mt][2] = __float_as_uint(As[buf][r    ][kb + tig + 4]);
                afr[mt][3] = __float_as_uint(As[buf][r + 8][kb + tig + 4]);
            }
            #pragma unroll
            for (int nt = 0; nt < 4; nt++) {
                int cn = n0 + nt * 8 + gid;
                bfr[nt][0] = __float_as_uint(Bs[buf][cn][kb + tig]);
                bfr[nt][1] = __float_as_uint(Bs[buf][cn][kb + tig + 4]);
            }
            #pragma unroll
            for (int mt = 0; mt < 2; mt++)
                #pragma unroll
                for (int nt = 0; nt < 4; nt++)
                    mma_tf32(acc[mt][nt], afr[mt], bfr[nt]);
        }
    }

    #pragma unroll
    for (int mt = 0; mt < 2; mt++) {
        int r = bm + m0 + mt * 16 + gid;
        #pragma unroll
        for (int nt = 0; nt < 4; nt++) {
            int nb = bn + n0 + nt * 8;
            if (nb < N) {
                int cn = nb + tig * 2;
                *(float2*)&C[(size_t)r * N + cn]       = make_float2(acc[mt][nt][0], acc[mt][nt][1]);
                *(float2*)&C[(size_t)(r + 8) * N + cn] = make_float2(acc[mt][nt][2], acc[mt][nt][3]);
            }
        }
    }
}

// ---------------- fused conv+silu -> u (smem+gmem) -> x_proj GEMM -> g_xdbl ----------------
// 128 thr. Block = (seq n, 64-t chunk). smem: us[64][260] + Bs[40][260] = 108160 B dynamic.
__global__ void __launch_bounds__(128) convxproj_kernel(
    const float* __restrict__ xpw, const float* __restrict__ cw, const float* __restrict__ cb)
{
    extern __shared__ float sm[];
    float* us = sm;                 // [64][260]
    float* Bsm = sm + 64 * 260;     // [40][260]
    int tid = threadIdx.x;
    int n = blockIdx.x >> 2, t0 = (blockIdx.x & 3) * 64;
    int R0 = n * TT + t0;

    // issue x_proj weight load: 40 rows x 64 float4 = 2560 f4 / 128 thr = 20 each
    #pragma unroll
    for (int i = 0; i < 20; i++) {
        int idx = tid + i * 128;
        int row = idx >> 6, c4 = (idx & 63) << 2;
        uint32_t dst = smem_u32(&Bsm[row * 260 + c4]);
        asm volatile("cp.async.cg.shared.global [%0], [%1], 16;" ::
                     "r"(dst), "l"(xpw + (size_t)row * 256 + c4));
    }
    asm volatile("cp.async.commit_group;");

    // conv+silu for channels d0=tid, d1=tid+128
    {
        int d0 = tid, d1 = tid + 128;
        float wA0 = cw[d0 * 4], wA1 = cw[d0 * 4 + 1], wA2 = cw[d0 * 4 + 2], wA3 = cw[d0 * 4 + 3];
        float wB0 = cw[d1 * 4], wB1 = cw[d1 * 4 + 1], wB2 = cw[d1 * 4 + 2], wB3 = cw[d1 * 4 + 3];
        float bA = cb[d0], bB = cb[d1];
        const float* xp = g_xz + (size_t)R0 * 512;
        float* up = g_u + (size_t)R0 * 256;
        float xA0, xA1, xA2, xB0, xB1, xB2;
        if (t0 >= 3) {
            xA0 = xp[-3 * 512 + d0]; xA1 = xp[-2 * 512 + d0]; xA2 = xp[-1 * 512 + d0];
            xB0 = xp[-3 * 512 + d1]; xB1 = xp[-2 * 512 + d1]; xB2 = xp[-1 * 512 + d1];
        } else {
            xA0 = xA1 = xA2 = xB0 = xB1 = xB2 = 0.f;
        }
        for (int tt = 0; tt < 64; tt += 4) {
            float aA0 = xp[(size_t)(tt + 0) * 512 + d0];
            float aA1 = xp[(size_t)(tt + 1) * 512 + d0];
            float aA2 = xp[(size_t)(tt + 2) * 512 + d0];
            float aA3 = xp[(size_t)(tt + 3) * 512 + d0];
            float aB0 = xp[(size_t)(tt + 0) * 512 + d1];
            float aB1 = xp[(size_t)(tt + 1) * 512 + d1];
            float aB2 = xp[(size_t)(tt + 2) * 512 + d1];
            float aB3 = xp[(size_t)(tt + 3) * 512 + d1];
            float s;
            #define EMIT(j, V) \
                us[(tt + j) * 260 + d0] = V; up[(size_t)(tt + j) * 256 + d0] = V;
            #define EMIT2(j, V) \
                us[(tt + j) * 260 + d1] = V; up[(size_t)(tt + j) * 256 + d1] = V;
            s = wA0 * xA0 + wA1 * xA1 + wA2 * xA2 + wA3 * aA0 + bA; s = s / (1.f + __expf(-s)); EMIT(0, s)
            s = wA0 * xA1 + wA1 * xA2 + wA2 * aA0 + wA3 * aA1 + bA; s = s / (1.f + __expf(-s)); EMIT(1, s)
            s = wA0 * xA2 + wA1 * aA0 + wA2 * aA1 + wA3 * aA2 + bA; s = s / (1.f + __expf(-s)); EMIT(2, s)
            s = wA0 * aA0 + wA1 * aA1 + wA2 * aA2 + wA3 * aA3 + bA; s = s / (1.f + __expf(-s)); EMIT(3, s)
            s = wB0 * xB0 + wB1 * xB1 + wB2 * xB2 + wB3 * aB0 + bB; s = s / (1.f + __expf(-s)); EMIT2(0, s)
            s = wB0 * xB1 + wB1 * xB2 + wB2 * aB0 + wB3 * aB1 + bB; s = s / (1.f + __expf(-s)); EMIT2(1, s)
            s = wB0 * xB2 + wB1 * aB0 + wB2 * aB1 + wB3 * aB2 + bB; s = s / (1.f + __expf(-s)); EMIT2(2, s)
            s = wB0 * aB0 + wB1 * aB1 + wB2 * aB2 + wB3 * aB3 + bB; s = s / (1.f + __expf(-s)); EMIT2(3, s)
            #undef EMIT
            #undef EMIT2
            xA0 = aA1; xA1 = aA2; xA2 = aA3;
            xB0 = aB1; xB1 = aB2; xB2 = aB3;
        }
    }
    asm volatile("cp.async.wait_group 0;");
    __syncthreads();

    // GEMM: us[64x256] @ Bsm[40x256]^T -> g_xdbl rows R0..R0+63
    int warp = tid >> 5, lane = tid & 31;
    int gid = lane >> 2, tig = lane & 3;
    int m0 = (warp & 1) * 32, n0 = (warp >> 1) * 32;

    float acc[2][4][4];
    #pragma unroll
    for (int i = 0; i < 2; i++)
        #pragma unroll
        for (int j = 0; j < 4; j++)
            #pragma unroll
            for (int k = 0; k < 4; k++) acc[i][j][k] = 0.f;

    #pragma unroll 8
    for (int kb = 0; kb < 256; kb += 8) {
        uint32_t afr[2][4], bfr[4][2];
        #pragma unroll
        for (int mt = 0; mt < 2; mt++) {
            int r = m0 + mt * 16 + gid;
            afr[mt][0] = __float_as_uint(us[r * 260 + kb + tig]);
            afr[mt][1] = __float_as_uint(us[(r + 8) * 260 + kb + tig]);
            afr[mt][2] = __float_as_uint(us[r * 260 + kb + tig + 4]);
            afr[mt][3] = __float_as_uint(us[(r + 8) * 260 + kb + tig + 4]);
        }
        #pragma unroll
        for (int nt = 0; nt < 4; nt++) {
            int ntile = n0 + nt * 8;
            if (ntile < 40) {
                int cn = ntile + gid;
                bfr[nt][0] = __float_as_uint(Bsm[cn * 260 + kb + tig]);
                bfr[nt][1] = __float_as_uint(Bsm[cn * 260 + kb + tig + 4]);
            }
        }
        #pragma unroll
        for (int mt = 0; mt < 2; mt++)
            #pragma unroll
            for (int nt = 0; nt < 4; nt++)
                if (n0 + nt * 8 < 40)
                    mma_tf32(acc[mt][nt], afr[mt], bfr[nt]);
    }

    #pragma unroll
    for (int mt = 0; mt < 2; mt++) {
        int r = R0 + m0 + mt * 16 + gid;
        #pragma unroll
        for (int nt = 0; nt < 4; nt++) {
            int nb = n0 + nt * 8;
            if (nb < 40) {
                int cn = nb + tig * 2;
                *(float2*)&g_xdbl[(size_t)r * 40 + cn]       = make_float2(acc[mt][nt][0], acc[mt][nt][1]);
                *(float2*)&g_xdbl[(size_t)(r + 8) * 40 + cn] = make_float2(acc[mt][nt][2], acc[mt][nt][3]);
            }
        }
    }
}

// ---------------- fused out_proj GEMM + residual + LayerNorm (1-sync pipeline) ----------------
__global__ void __launch_bounds__(256) outproj_ln_kernel(
    const float* __restrict__ A, const float* __restrict__ B,
    const float* __restrict__ nw, const float* __restrict__ nb)
{
    const int BK = 16, K = DII;
    __shared__ float As[2][64][BK + 4];
    __shared__ float Bs[2][DMM][BK + 4];
    __shared__ float Cs[64][DMM + 4];

    int tid  = threadIdx.x;
    int bm   = blockIdx.x * 64;
    int warp = tid >> 5, lane = tid & 31;
    int gid  = lane >> 2, tig = lane & 3;
    int m0   = (warp & 1) * 32;
    int n0   = (warp >> 1) * 32;

    float acc[2][4][4];
    #pragma unroll
    for (int i = 0; i < 2; i++)
        #pragma unroll
        for (int j = 0; j < 4; j++)
            #pragma unroll
            for (int k = 0; k < 4; k++) acc[i][j][k] = 0.f;

    int arow = tid >> 2, akq = (tid & 3) * 4;
    int brow = tid >> 1, bkq = (tid & 1) * 8;
    const float* aptr = A + (size_t)(bm + arow) * K + akq;
    const float* bptr = B + (size_t)brow * K + bkq;
    const int nk = K / BK;

    {
        uint32_t da  = smem_u32(&As[0][arow][akq]);
        uint32_t db0 = smem_u32(&Bs[0][brow][bkq]);
        uint32_t db1 = smem_u32(&Bs[0][brow][bkq + 4]);
        asm volatile("cp.async.cg.shared.global [%0], [%1], 16;" :: "r"(da),  "l"(aptr));
        asm volatile("cp.async.cg.shared.global [%0], [%1], 16;" :: "r"(db0), "l"(bptr));
        asm volatile("cp.async.cg.shared.global [%0], [%1], 16;" :: "r"(db1), "l"(bptr + 4));
        asm volatile("cp.async.commit_group;");
    }

    for (int i = 0; i < nk; i++) {
        int buf = i & 1;
        asm volatile("cp.async.wait_group 0;");
        __syncthreads();
        if (i + 1 < nk) {
            int k0 = (i + 1) * BK;
            uint32_t da  = smem_u32(&As[buf ^ 1][arow][akq]);
            uint32_t db0 = smem_u32(&Bs[buf ^ 1][brow][bkq]);
            uint32_t db1 = smem_u32(&Bs[buf ^ 1][brow][bkq + 4]);
            asm volatile("cp.async.cg.shared.global [%0], [%1], 16;" :: "r"(da),  "l"(aptr + k0));
            asm volatile("cp.async.cg.shared.global [%0], [%1], 16;" :: "r"(db0), "l"(bptr + k0));
            asm volatile("cp.async.cg.shared.global [%0], [%1], 16;" :: "r"(db1), "l"(bptr + k0 + 4));
            asm volatile("cp.async.commit_group;");
        }
        #pragma unroll
        for (int c = 0; c < 2; c++) {
            int kb = c * 8;
            uint32_t afr[2][4], bfr[4][2];
            #pragma unroll
            for (int mt = 0; mt < 2; mt++) {
                int r = m0 + mt * 16 + gid;
                afr[mt][0] = __float_as_uint(As[buf][r    ][kb + tig]);
                afr[mt][1] = __float_as_uint(As[buf][r + 8][kb + tig]);
                afr[mt][2] = __float_as_uint(As[buf][r    ][kb + tig + 4]);
                afr[mt][3] = __float_as_uint(As[buf][r + 8][kb + tig + 4]);
            }
            #pragma unroll
            for (int nt = 0; nt < 4; nt++) {
                int cn = n0 + nt * 8 + gid;
                bfr[nt][0] = __float_as_uint(Bs[buf][cn][kb + tig]);
                bfr[nt][1] = __float_as_uint(Bs[buf][cn][kb + tig + 4]);
            }
            #pragma unroll
            for (int mt = 0; mt < 2; mt++)
                #pragma unroll
                for (int nt = 0; nt < 4; nt++)
                    mma_tf32(acc[mt][nt], afr[mt], bfr[nt]);
        }
    }

    #pragma unroll
    for (int mt = 0; mt < 2; mt++) {
        int r = m0 + mt * 16 + gid;
        #pragma unroll
        for (int nt = 0; nt < 4; nt++) {
            int cn = n0 + nt * 8 + tig * 2;
            *(float2*)&Cs[r    ][cn] = make_float2(acc[mt][nt][0], acc[mt][nt][1]);
            *(float2*)&Cs[r + 8][cn] = make_float2(acc[mt][nt][2], acc[mt][nt][3]);
        }
    }
    __syncthreads();

    float w0 = nw[lane], w1 = nw[lane + 32], w2 = nw[lane + 64], w3 = nw[lane + 96];
    float b0 = nb[lane], b1 = nb[lane + 32], b2 = nb[lane + 64], b3 = nb[lane + 96];
    for (int rr = warp * 8; rr < warp * 8 + 8; rr++) {
        size_t gr = (size_t)(bm + rr) * DMM;
        float v0 = Cs[rr][lane]      + g_h[gr + lane];
        float v1 = Cs[rr][lane + 32] + g_h[gr + lane + 32];
        float v2 = Cs[rr][lane + 64] + g_h[gr + lane + 64];
        float v3 = Cs[rr][lane + 96] + g_h[gr + lane + 96];
        float s = v0 + v1 + v2 + v3;
        float q = v0 * v0 + v1 * v1 + v2 * v2 + v3 * v3;
        #pragma unroll
        for (int o = 16; o; o >>= 1) {
            s += __shfl_xor_sync(0xffffffffu, s, o);
            q += __shfl_xor_sync(0xffffffffu, q, o);
        }
        float mu = s * (1.0f / DMM);
        float var = q * (1.0f / DMM) - mu * mu;
        float rs = rsqrtf(var + LNEPS);
        g_h[gr + lane]      = (v0 - mu) * rs * w0 + b0;
        g_h[gr + lane + 32] = (v1 - mu) * rs * w1 + b1;
        g_h[gr + lane + 64] = (v2 - mu) * rs * w2 + b2;
        g_h[gr + lane + 96] = (v3 - mu) * rs * w3 + b3;
    }
}

// ---------------- selective scan ----------------
__global__ void __launch_bounds__(128) scan_kernel(
    const float* __restrict__ dtw, const float* __restrict__ dtb,
    const float* __restrict__ alog, const float* __restrict__ Dv)
{
    int n = blockIdx.x;
    int tid = threadIdx.x;
    int d = blockIdx.y * 128 + tid;

    __shared__ float4 sx4[TT * 10];
    {
        const float4* src = (const float4*)(g_xdbl + (size_t)n * TT * 40);
        #pragma unroll
        for (int i = 0; i < 20; i++) {
            int idx = tid + i * 128;
            uint32_t dst = smem_u32(&sx4[idx]);
            asm volatile("cp.async.cg.shared.global [%0], [%1], 16;" :: "r"(dst), "l"(src + idx));
        }
        asm volatile("cp.async.commit_group;");
    }

    float A[DSS], hst[DSS], wdt[DTRR];
    bool fastA = true;
    #pragma unroll
    for (int s = 0; s < DSS; s++) {
        A[s] = -__expf(alog[d * DSS + s]);
        hst[s] = 0.f;
        fastA = fastA && (A[s] == -(float)(s + 1));
    }
    #pragma unroll
    for (int j = 0; j < DTRR; j++) wdt[j] = dtw[d * DTRR + j];
    float dtbd = dtb[d], Dd = Dv[d];

    const size_t base_u = (size_t)n * TT * DII + d;
    const size_t base_z = (size_t)n * TT * 2 * DII + DII + d;

    float u0 = g_u[base_u],           z0 = g_xz[base_z];
    float u1 = g_u[base_u + DII],     z1 = g_xz[base_z + 2 * DII];
    float u2 = g_u[base_u + 2 * DII], z2 = g_xz[base_z + 4 * DII];

    asm volatile("cp.async.wait_group 0;");
    __syncthreads();

    const float* sxa = (const float*)sx4;
    for (int t = 0; t < TT; t++) {
        float u3 = 0.f, z3 = 0.f;
        if (t + 3 < TT) {
            u3 = g_u[base_u + (size_t)(t + 3) * DII];
            z3 = g_xz[base_z + (size_t)(t + 3) * 2 * DII];
        }
        const float4* sc4 = (const float4*)(sxa + t * 40);
        float4 dA = sc4[0], dB = sc4[1];
        float4 Bv0 = sc4[2], Bv1 = sc4[3], Bv2 = sc4[4], Bv3 = sc4[5];
        float4 Cv0 = sc4[6], Cv1 = sc4[7], Cv2 = sc4[8], Cv3 = sc4[9];
        float Bf[16] = {Bv0.x,Bv0.y,Bv0.z,Bv0.w, Bv1.x,Bv1.y,Bv1.z,Bv1.w,
                        Bv2.x,Bv2.y,Bv2.z,Bv2.w, Bv3.x,Bv3.y,Bv3.z,Bv3.w};
        float Cf[16] = {Cv0.x,Cv0.y,Cv0.z,Cv0.w, Cv1.x,Cv1.y,Cv1.z,Cv1.w,
                        Cv2.x,Cv2.y,Cv2.z,Cv2.w, Cv3.x,Cv3.y,Cv3.z,Cv3.w};
        float a0 = dA.x * wdt[0] + dA.y * wdt[1];
        float a1 = dA.z * wdt[2] + dA.w * wdt[3];
        float a2 = dB.x * wdt[4] + dB.y * wdt[5];
        float a3 = dB.z * wdt[6] + dB.w * wdt[7];
        float dtv = dtbd + ((a0 + a1) + (a2 + a3));
        float delta = (dtv > 15.f) ? dtv : __logf(1.f + __expf(dtv));
        float du = delta * u0;
        float y0 = 0.f, y1 = 0.f, y2 = 0.f, y3 = 0.f;
        if (fastA) {
            float p1 = __expf(-delta);
            float p2 = p1 * p1;
            float p3 = p2 * p1, p4 = p2 * p2;
            float p5 = p4 * p1, p6 = p4 * p2, p7 = p4 * p3, p8 = p4 * p4;
            float e[16];
            e[0] = p1; e[1] = p2; e[2] = p3; e[3] = p4;
            e[4] = p5; e[5] = p6; e[6] = p7; e[7] = p8;
            e[8]  = p8 * p1; e[9]  = p8 * p2; e[10] = p8 * p3; e[11] = p8 * p4;
            e[12] = p8 * p5; e[13] = p8 * p6; e[14] = p8 * p7; e[15] = p8 * p8;
            #pragma unroll
            for (int s = 0; s < DSS; s += 4) {
                hst[s]     = e[s]     * hst[s]     + du * Bf[s];
                hst[s + 1] = e[s + 1] * hst[s + 1] + du * Bf[s + 1];
                hst[s + 2] = e[s + 2] * hst[s + 2] + du * Bf[s + 2];
                hst[s + 3] = e[s + 3] * hst[s + 3] + du * Bf[s + 3];
                y0 += hst[s] * Cf[s];
                y1 += hst[s + 1] * Cf[s + 1];
                y2 += hst[s + 2] * Cf[s + 2];
                y3 += hst[s + 3] * Cf[s + 3];
            }
        } else {
            #pragma unroll
            for (int s = 0; s < DSS; s += 4) {
                #pragma unroll
                for (int j = 0; j < 4; j++) {
                    float e = __expf(delta * A[s + j]);
                    hst[s + j] = e * hst[s + j] + du * Bf[s + j];
                }
                y0 += hst[s] * Cf[s];
                y1 += hst[s + 1] * Cf[s + 1];
                y2 += hst[s + 2] * Cf[s + 2];
                y3 += hst[s + 3] * Cf[s + 3];
            }
        }
        float y = ((y0 + y1) + (y2 + y3)) + u0 * Dd;
        float sz = z0 / (1.f + __expf(-z0));
        g_ym[base_u + (size_t)t * DII] = y * sz;
        u0 = u1; u1 = u2; u2 = u3;
        z0 = z1; z1 = z2; z2 = z3;
    }
}

// ---------------- final layernorm + mean over T ----------------
__global__ void __launch_bounds__(128) final_partial_kernel(
    const float* __restrict__ w, const float* __restrict__ b)
{
    int n = blockIdx.x, t0 = blockIdx.y * 64, d = threadIdx.x;
    float wd = w[d], bd = b[d], acc = 0.f;
    for (int tt = 0; tt < 64; tt++) {
        float v = g_h[(size_t)(n * TT + t0 + tt) * DMM + d];
        float mu, var;
        row_stats128(v, mu, var);
        acc += (v - mu) * rsqrtf(var + LNEPS) * wd + bd;
    }
    g_part[(size_t)(n * 4 + blockIdx.y) * DMM + d] = acc;
}

__global__ void __launch_bounds__(128) final_combine_kernel(float* __restrict__ out)
{
    int n = blockIdx.x, d = threadIdx.x;
    float s = g_part[(size_t)(n * 4 + 0) * DMM + d]
            + g_part[(size_t)(n * 4 + 1) * DMM + d]
            + g_part[(size_t)(n * 4 + 2) * DMM + d]
            + g_part[(size_t)(n * 4 + 3) * DMM + d];
    out[(size_t)n * DMM + d] = s * (1.0f / TT);
}

// ---------------- launch ----------------
extern "C" void kernel_launch(void* const* d_in, const int* in_sizes, int n_in,
                              void* d_out, int out_size)
{
    (void)in_sizes; (void)n_in; (void)out_size;
    const float* x     = (const float*)d_in[0];
    const float* inp_w = (const float*)d_in[1];
    const float* inp_b = (const float*)d_in[2];
    const float* ipw   = (const float*)d_in[3];
    const float* cw    = (const float*)d_in[4];
    const float* cb    = (const float*)d_in[5];
    const float* xpw   = (const float*)d_in[6];
    const float* dtw   = (const float*)d_in[7];
    const float* dtb   = (const float*)d_in[8];
    const float* alog  = (const float*)d_in[9];
    const float* Dv    = (const float*)d_in[10];
    const float* opw   = (const float*)d_in[11];
    const float* nw    = (const float*)d_in[12];
    const float* nb    = (const float*)d_in[13];
    const float* onw   = (const float*)d_in[14];
    const float* onb   = (const float*)d_in[15];
    float* out = (float*)d_out;

    float *ph, *pxz, *pym;
    cudaGetSymbolAddress((void**)&ph,  g_h);
    cudaGetSymbolAddress((void**)&pxz, g_xz);
    cudaGetSymbolAddress((void**)&pym, g_ym);

    const int SMEM_IP = (64 * 68 + 128 * 68) * 4;          // 52224
    const int SMEM_CX = (64 * 260 + 40 * 260) * 4;         // 108160
    cudaFuncSetAttribute(input_proj_mma, cudaFuncAttributeMaxDynamicSharedMemorySize, SMEM_IP);
    cudaFuncSetAttribute(convxproj_kernel, cudaFuncAttributeMaxDynamicSharedMemorySize, SMEM_CX);

    input_proj_mma<<<dim3(NSEQ, 4), 256, SMEM_IP>>>(x, inp_w, inp_b);

    for (int l = 0; l < 2; l++) {
        // xz = h @ in_proj_w^T  [16384,512], K=128
        mma_gemm_kernel<<<dim3(ROWS / 64, 8), 128>>>(
            ph, ipw + (size_t)l * 2 * DII * DMM, pxz, ROWS, 2 * DII, DMM);
        // fused conv+silu + x_proj GEMM
        convxproj_kernel<<<NSEQ * 4, 128, SMEM_CX>>>(
            xpw + (size_t)l * 40 * DII, cw + (size_t)l * DII * 4, cb + (size_t)l * DII);
        // fused scan
        scan_kernel<<<dim3(NSEQ, 2), 128>>>(dtw + (size_t)l * DII * DTRR, dtb + (size_t)l * DII,
                                            alog + (size_t)l * DII * DSS, Dv + (size_t)l * DII);
        // h = LN(h + ym @ out_proj_w^T)
        outproj_ln_kernel<<<ROWS / 64, 256>>>(
            pym, opw + (size_t)l * DMM * DII, nw + (size_t)l * DMM, nb + (size_t)l * DMM);
    }

    final_partial_kernel<<<dim3(NSEQ, 4), 128>>>(onw, onb);
    final_combine_kernel<<<NSEQ, 128>>>(out);
}

// round 5
// speedup vs baseline: 2.1154x; 1.0568x over previous
#include <cuda_runtime.h>
#include <math.h>
#include <stdint.h>

#define NSEQ 64
#define TT   256
#define FF   64
#define DMM  128
#define DII  256
#define DSS  16
#define DTRR 8
#define ROWS (NSEQ*TT)
#define LNEPS 1e-5f
#define CHK  16

// ---------------- scratch ----------------
__device__ float  g_h   [ROWS*DMM];
__device__ float  g_xz  [ROWS*2*DII];
__device__ float  g_xdbl[ROWS*40];
__device__ float4 g_coef[ROWS*DII];     // (du, p, sz, uD) per (row, d)
__device__ float  g_ym  [ROWS*DII];
__device__ float  g_part[NSEQ*4*DMM];

// ---------------- helpers ----------------
__device__ __forceinline__ uint32_t smem_u32(const void* p) {
    return (uint32_t)__cvta_generic_to_shared(p);
}
__device__ __forceinline__ void mma_tf32(float* c, const uint32_t* a, const uint32_t* b) {
    asm volatile(
        "mma.sync.aligned.m16n8k8.row.col.f32.tf32.tf32.f32 "
        "{%0,%1,%2,%3}, {%4,%5,%6,%7}, {%8,%9}, {%0,%1,%2,%3};"
        : "+f"(c[0]), "+f"(c[1]), "+f"(c[2]), "+f"(c[3])
        : "r"(a[0]), "r"(a[1]), "r"(a[2]), "r"(a[3]), "r"(b[0]), "r"(b[1]));
}
__device__ __forceinline__ void row_stats128(float v, float& mu, float& var) {
    float s = v, q = v * v;
    #pragma unroll
    for (int o = 16; o; o >>= 1) {
        s += __shfl_down_sync(0xffffffffu, s, o);
        q += __shfl_down_sync(0xffffffffu, q, o);
    }
    __shared__ float ss[4], sq[4];
    int w = threadIdx.x >> 5;
    if ((threadIdx.x & 31) == 0) { ss[w] = s; sq[w] = q; }
    __syncthreads();
    s = ss[0] + ss[1] + ss[2] + ss[3];
    q = sq[0] + sq[1] + sq[2] + sq[3];
    __syncthreads();
    mu  = s * (1.0f / DMM);
    var = q * (1.0f / DMM) - mu * mu;
}

// ---------------- tensorized input projection ----------------
__global__ void __launch_bounds__(256) input_proj_mma(
    const float* __restrict__ x, const float* __restrict__ w, const float* __restrict__ bias)
{
    extern __shared__ float sm[];
    float* As = sm;              // [64 t][68]
    float* Bs = sm + 64 * 68;    // [128 d][68]
    int n = blockIdx.x, t0 = blockIdx.y * 64;
    int tid = threadIdx.x;

    #pragma unroll
    for (int p = 0; p < 4; p++) {
        int f = p * 16 + (tid >> 4), t4 = (tid & 15) * 4;
        float4 v = *(const float4*)(x + ((size_t)(n * FF + f)) * TT + t0 + t4);
        As[(t4 + 0) * 68 + f] = v.x;
        As[(t4 + 1) * 68 + f] = v.y;
        As[(t4 + 2) * 68 + f] = v.z;
        As[(t4 + 3) * 68 + f] = v.w;
    }
    #pragma unroll
    for (int i = 0; i < 8; i++) {
        int idx = tid + i * 256;
        int row = idx >> 4, c4 = (idx & 15) << 2;
        *(float4*)&Bs[row * 68 + c4] = *(const float4*)(w + row * 64 + c4);
    }
    __syncthreads();

    int warp = tid >> 5, lane = tid & 31;
    int gid = lane >> 2, tig = lane & 3;
    int m0 = (warp & 1) * 32, n0 = (warp >> 1) * 32;

    float acc[2][4][4];
    #pragma unroll
    for (int i = 0; i < 2; i++)
        #pragma unroll
        for (int j = 0; j < 4; j++)
            #pragma unroll
            for (int k = 0; k < 4; k++) acc[i][j][k] = 0.f;

    #pragma unroll
    for (int kb = 0; kb < 64; kb += 8) {
        uint32_t afr[2][4], bfr[4][2];
        #pragma unroll
        for (int mt = 0; mt < 2; mt++) {
            int r = m0 + mt * 16 + gid;
            afr[mt][0] = __float_as_uint(As[r * 68 + kb + tig]);
            afr[mt][1] = __float_as_uint(As[(r + 8) * 68 + kb + tig]);
            afr[mt][2] = __float_as_uint(As[r * 68 + kb + tig + 4]);
            afr[mt][3] = __float_as_uint(As[(r + 8) * 68 + kb + tig + 4]);
        }
        #pragma unroll
        for (int nt = 0; nt < 4; nt++) {
            int cn = n0 + nt * 8 + gid;
            bfr[nt][0] = __float_as_uint(Bs[cn * 68 + kb + tig]);
            bfr[nt][1] = __float_as_uint(Bs[cn * 68 + kb + tig + 4]);
        }
        #pragma unroll
        for (int mt = 0; mt < 2; mt++)
            #pragma unroll
            for (int nt = 0; nt < 4; nt++)
                mma_tf32(acc[mt][nt], afr[mt], bfr[nt]);
    }

    #pragma unroll
    for (int mt = 0; mt < 2; mt++) {
        int r = n * TT + t0 + m0 + mt * 16 + gid;
        #pragma unroll
        for (int nt = 0; nt < 4; nt++) {
            int cn = n0 + nt * 8 + tig * 2;
            float2 bv = *(const float2*)(bias + cn);
            *(float2*)&g_h[(size_t)r * DMM + cn] =
                make_float2(acc[mt][nt][0] + bv.x, acc[mt][nt][1] + bv.y);
            *(float2*)&g_h[(size_t)(r + 8) * DMM + cn] =
                make_float2(acc[mt][nt][2] + bv.x, acc[mt][nt][3] + bv.y);
        }
    }
}

// ---------------- tf32 GEMM (in_proj): C=A@B^T, BM=BN=64, BK=16, 128 thr ----------------
__global__ void __launch_bounds__(128) mma_gemm_kernel(
    const float* __restrict__ A, const float* __restrict__ B, float* __restrict__ C,
    int M, int N, int K)
{
    const int BK = 16;
    __shared__ float As[2][64][BK + 4];
    __shared__ float Bs[2][64][BK + 4];

    int tid  = threadIdx.x;
    int bm   = blockIdx.x * 64, bn = blockIdx.y * 64;
    int warp = tid >> 5, lane = tid & 31;
    int gid  = lane >> 2, tig = lane & 3;
    int m0   = (warp & 1) * 32;
    int n0   = (warp >> 1) * 32;

    float acc[2][4][4];
    #pragma unroll
    for (int i = 0; i < 2; i++)
        #pragma unroll
        for (int j = 0; j < 4; j++)
            #pragma unroll
            for (int k = 0; k < 4; k++) acc[i][j][k] = 0.f;

    int arow = tid >> 1, akq = (tid & 1) * 8;
    const float* aptr = A + (size_t)(bm + arow) * K + akq;
    const float* bptr = B + (size_t)(bn + arow) * K + akq;
    int bsz = ((bn + arow) < N) ? 16 : 0;
    int nk = K / BK;

    {
        uint32_t da0 = smem_u32(&As[0][arow][akq]);
        uint32_t da1 = smem_u32(&As[0][arow][akq + 4]);
        uint32_t db0 = smem_u32(&Bs[0][arow][akq]);
        uint32_t db1 = smem_u32(&Bs[0][arow][akq + 4]);
        asm volatile("cp.async.cg.shared.global [%0], [%1], 16;" :: "r"(da0), "l"(aptr));
        asm volatile("cp.async.cg.shared.global [%0], [%1], 16;" :: "r"(da1), "l"(aptr + 4));
        asm volatile("cp.async.cg.shared.global [%0], [%1], 16, %2;" :: "r"(db0), "l"(bptr), "r"(bsz));
        asm volatile("cp.async.cg.shared.global [%0], [%1], 16, %2;" :: "r"(db1), "l"(bptr + 4), "r"(bsz));
        asm volatile("cp.async.commit_group;");
    }

    for (int i = 0; i < nk; i++) {
        int buf = i & 1;
        asm volatile("cp.async.wait_group 0;");
        __syncthreads();
        if (i + 1 < nk) {
            int k0 = (i + 1) * BK;
            uint32_t da0 = smem_u32(&As[buf ^ 1][arow][akq]);
            uint32_t da1 = smem_u32(&As[buf ^ 1][arow][akq + 4]);
            uint32_t db0 = smem_u32(&Bs[buf ^ 1][arow][akq]);
            uint32_t db1 = smem_u32(&Bs[buf ^ 1][arow][akq + 4]);
            asm volatile("cp.async.cg.shared.global [%0], [%1], 16;" :: "r"(da0), "l"(aptr + k0));
            asm volatile("cp.async.cg.shared.global [%0], [%1], 16;" :: "r"(da1), "l"(aptr + k0 + 4));
            asm volatile("cp.async.cg.shared.global [%0], [%1], 16, %2;" :: "r"(db0), "l"(bptr + k0), "r"(bsz));
            asm volatile("cp.async.cg.shared.global [%0], [%1], 16, %2;" :: "r"(db1), "l"(bptr + k0 + 4), "r"(bsz));
            asm volatile("cp.async.commit_group;");
        }
        #pragma unroll
        for (int c = 0; c < 2; c++) {
            int kb = c * 8;
            uint32_t afr[2][4], bfr[4][2];
            #pragma unroll
            for (int mt = 0; mt < 2; mt++) {
                int r = m0 + mt * 16 + gid;
                afr[mt][0] = __float_as_uint(As[buf][r    ][kb + tig]);
                afr[mt][1] = __float_as_uint(As[buf][r + 8][kb + tig]);
                afr[mt][2] = __float_as_uint(As[buf][r    ][kb + tig + 4]);
                afr[mt][3] = __float_as_uint(As[buf][r + 8][kb + tig + 4]);
            }
            #pragma unroll
            for (int nt = 0; nt < 4; nt++) {
                int cn = n0 + nt * 8 + gid;
                bfr[nt][0] = __float_as_uint(Bs[buf][cn][kb + tig]);
                bfr[nt][1] = __float_as_uint(Bs[buf][cn][kb + tig + 4]);
            }
            #pragma unroll
            for (int mt = 0; mt < 2; mt++)
                #pragma unroll
                for (int nt = 0; nt < 4; nt++)
                    mma_tf32(acc[mt][nt], afr[mt], bfr[nt]);
        }
    }

    #pragma unroll
    for (int mt = 0; mt < 2; mt++) {
        int r = bm + m0 + mt * 16 + gid;
        #pragma unroll
        for (int nt = 0; nt < 4; nt++) {
            int nb = bn + n0 + nt * 8;
            if (nb < N) {
                int cn = nb + tig * 2;
                *(float2*)&C[(size_t)r * N + cn]       = make_float2(acc[mt][nt][0], acc[mt][nt][1]);
                *(float2*)&C[(size_t)(r + 8) * N + cn] = make_float2(acc[mt][nt][2], acc[mt][nt][3]);
            }
        }
    }
}

// ---- fused conv+silu -> x_proj GEMM -> dt-proj + coefficient precompute ----
// 128 thr. Block = (seq n, 64-t chunk). smem: us[64][260] + Bsm[40][260] (reused as xds).
__global__ void __launch_bounds__(128) convxproj_kernel(
    const float* __restrict__ xpw, const float* __restrict__ cw, const float* __restrict__ cb,
    const float* __restrict__ dtw, const float* __restrict__ dtb, const float* __restrict__ Dv)
{
    extern __shared__ float sm[];
    float* us  = sm;                // [64][260]
    float* Bsm = sm + 64 * 260;     // [40][260], reused as xds[64][44] after GEMM
    int tid = threadIdx.x;
    int n = blockIdx.x >> 2, t0 = (blockIdx.x & 3) * 64;
    int R0 = n * TT + t0;

    // x_proj weight load
    #pragma unroll
    for (int i = 0; i < 20; i++) {
        int idx = tid + i * 128;
        int row = idx >> 6, c4 = (idx & 63) << 2;
        uint32_t dst = smem_u32(&Bsm[row * 260 + c4]);
        asm volatile("cp.async.cg.shared.global [%0], [%1], 16;" ::
                     "r"(dst), "l"(xpw + (size_t)row * 256 + c4));
    }
    asm volatile("cp.async.commit_group;");

    // conv+silu for channels d0=tid, d1=tid+128 -> us (smem only)
    {
        int d0 = tid, d1 = tid + 128;
        float wA0 = cw[d0 * 4], wA1 = cw[d0 * 4 + 1], wA2 = cw[d0 * 4 + 2], wA3 = cw[d0 * 4 + 3];
        float wB0 = cw[d1 * 4], wB1 = cw[d1 * 4 + 1], wB2 = cw[d1 * 4 + 2], wB3 = cw[d1 * 4 + 3];
        float bA = cb[d0], bB = cb[d1];
        const float* xp = g_xz + (size_t)R0 * 512;
        float xA0, xA1, xA2, xB0, xB1, xB2;
        if (t0 >= 3) {
            xA0 = xp[-3 * 512 + d0]; xA1 = xp[-2 * 512 + d0]; xA2 = xp[-1 * 512 + d0];
            xB0 = xp[-3 * 512 + d1]; xB1 = xp[-2 * 512 + d1]; xB2 = xp[-1 * 512 + d1];
        } else {
            xA0 = xA1 = xA2 = xB0 = xB1 = xB2 = 0.f;
        }
        for (int tt = 0; tt < 64; tt += 4) {
            float aA0 = xp[(size_t)(tt + 0) * 512 + d0];
            float aA1 = xp[(size_t)(tt + 1) * 512 + d0];
            float aA2 = xp[(size_t)(tt + 2) * 512 + d0];
            float aA3 = xp[(size_t)(tt + 3) * 512 + d0];
            float aB0 = xp[(size_t)(tt + 0) * 512 + d1];
            float aB1 = xp[(size_t)(tt + 1) * 512 + d1];
            float aB2 = xp[(size_t)(tt + 2) * 512 + d1];
            float aB3 = xp[(size_t)(tt + 3) * 512 + d1];
            float s;
            s = wA0 * xA0 + wA1 * xA1 + wA2 * xA2 + wA3 * aA0 + bA; us[(tt + 0) * 260 + d0] = s / (1.f + __expf(-s));
            s = wA0 * xA1 + wA1 * xA2 + wA2 * aA0 + wA3 * aA1 + bA; us[(tt + 1) * 260 + d0] = s / (1.f + __expf(-s));
            s = wA0 * xA2 + wA1 * aA0 + wA2 * aA1 + wA3 * aA2 + bA; us[(tt + 2) * 260 + d0] = s / (1.f + __expf(-s));
            s = wA0 * aA0 + wA1 * aA1 + wA2 * aA2 + wA3 * aA3 + bA; us[(tt + 3) * 260 + d0] = s / (1.f + __expf(-s));
            s = wB0 * xB0 + wB1 * xB1 + wB2 * xB2 + wB3 * aB0 + bB; us[(tt + 0) * 260 + d1] = s / (1.f + __expf(-s));
            s = wB0 * xB1 + wB1 * xB2 + wB2 * aB0 + wB3 * aB1 + bB; us[(tt + 1) * 260 + d1] = s / (1.f + __expf(-s));
            s = wB0 * xB2 + wB1 * aB0 + wB2 * aB1 + wB3 * aB2 + bB; us[(tt + 2) * 260 + d1] = s / (1.f + __expf(-s));
            s = wB0 * aB0 + wB1 * aB1 + wB2 * aB2 + wB3 * aB3 + bB; us[(tt + 3) * 260 + d1] = s / (1.f + __expf(-s));
            xA0 = aA1; xA1 = aA2; xA2 = aA3;
            xB0 = aB1; xB1 = aB2; xB2 = aB3;
        }
    }
    asm volatile("cp.async.wait_group 0;");
    __syncthreads();

    // GEMM: us[64x256] @ Bsm[40x256]^T
    int warp = tid >> 5, lane = tid & 31;
    int gid = lane >> 2, tig = lane & 3;
    int m0 = (warp & 1) * 32, n0 = (warp >> 1) * 32;

    float acc[2][4][4];
    #pragma unroll
    for (int i = 0; i < 2; i++)
        #pragma unroll
        for (int j = 0; j < 4; j++)
            #pragma unroll
            for (int k = 0; k < 4; k++) acc[i][j][k] = 0.f;

    #pragma unroll 8
    for (int kb = 0; kb < 256; kb += 8) {
        uint32_t afr[2][4], bfr[4][2];
        #pragma unroll
        for (int mt = 0; mt < 2; mt++) {
            int r = m0 + mt * 16 + gid;
            afr[mt][0] = __float_as_uint(us[r * 260 + kb + tig]);
            afr[mt][1] = __float_as_uint(us[(r + 8) * 260 + kb + tig]);
            afr[mt][2] = __float_as_uint(us[r * 260 + kb + tig + 4]);
            afr[mt][3] = __float_as_uint(us[(r + 8) * 260 + kb + tig + 4]);
        }
        #pragma unroll
        for (int nt = 0; nt < 4; nt++) {
            int ntile = n0 + nt * 8;
            if (ntile < 40) {
                int cn = ntile + gid;
                bfr[nt][0] = __float_as_uint(Bsm[cn * 260 + kb + tig]);
                bfr[nt][1] = __float_as_uint(Bsm[cn * 260 + kb + tig + 4]);
            }
        }
        #pragma unroll
        for (int mt = 0; mt < 2; mt++)
            #pragma unroll
            for (int nt = 0; nt < 4; nt++)
                if (n0 + nt * 8 < 40)
                    mma_tf32(acc[mt][nt], afr[mt], bfr[nt]);
    }

    // per-thread dt weights for its d-quad (loaded before syncs, independent)
    int q  = tid & 63;          // d-quad: d = 4q .. 4q+3
    int rh = tid >> 6;          // row half
    float wq[4][8];
    #pragma unroll
    for (int j = 0; j < 4; j++) {
        float4 wa = *(const float4*)(dtw + (size_t)(q * 4 + j) * 8);
        float4 wb = *(const float4*)(dtw + (size_t)(q * 4 + j) * 8 + 4);
        wq[j][0] = wa.x; wq[j][1] = wa.y; wq[j][2] = wa.z; wq[j][3] = wa.w;
        wq[j][4] = wb.x; wq[j][5] = wb.y; wq[j][6] = wb.z; wq[j][7] = wb.w;
    }
    float4 dtb4 = *(const float4*)(dtb + q * 4);
    float4 Dv4  = *(const float4*)(Dv + q * 4);
    float dtbs[4] = {dtb4.x, dtb4.y, dtb4.z, dtb4.w};
    float Dvs[4]  = {Dv4.x, Dv4.y, Dv4.z, Dv4.w};

    __syncthreads();   // GEMM reads of Bsm complete before overwrite

    // frags -> g_xdbl (gmem, for scan's B/C) and xds (smem, for dt-proj)
    float* xds = Bsm;  // [64][44]
    #pragma unroll
    for (int mt = 0; mt < 2; mt++) {
        int r = m0 + mt * 16 + gid;
        #pragma unroll
        for (int nt = 0; nt < 4; nt++) {
            int nb = n0 + nt * 8;
            if (nb < 40) {
                int cn = nb + tig * 2;
                *(float2*)&g_xdbl[(size_t)(R0 + r) * 40 + cn] =
                    make_float2(acc[mt][nt][0], acc[mt][nt][1]);
                *(float2*)&g_xdbl[(size_t)(R0 + r + 8) * 40 + cn] =
                    make_float2(acc[mt][nt][2], acc[mt][nt][3]);
                *(float2*)&xds[r * 44 + cn]       = make_float2(acc[mt][nt][0], acc[mt][nt][1]);
                *(float2*)&xds[(r + 8) * 44 + cn] = make_float2(acc[mt][nt][2], acc[mt][nt][3]);
            }
        }
    }
    __syncthreads();

    // dt-proj + coefficient precompute: thread owns d-quad q, rows rh*32..rh*32+31
    for (int i = 0; i < 32; i++) {
        int row = rh * 32 + i;
        float4 da = *(float4*)&xds[row * 44];
        float4 db = *(float4*)&xds[row * 44 + 4];
        float4 u4 = *(float4*)&us[row * 260 + q * 4];
        float4 z4 = *(const float4*)&g_xz[(size_t)(R0 + row) * 512 + 256 + q * 4];
        float uu[4] = {u4.x, u4.y, u4.z, u4.w};
        float zz[4] = {z4.x, z4.y, z4.z, z4.w};
        #pragma unroll
        for (int j = 0; j < 4; j++) {
            float dtv = dtbs[j]
                + da.x * wq[j][0] + da.y * wq[j][1] + da.z * wq[j][2] + da.w * wq[j][3]
                + db.x * wq[j][4] + db.y * wq[j][5] + db.z * wq[j][6] + db.w * wq[j][7];
            float pp, delta;
            if (dtv > 15.f) { delta = dtv; pp = __expf(-dtv); }
            else {
                float e1 = __expf(dtv);
                pp = 1.f / (1.f + e1);            // exp(-softplus(dtv))
                delta = -__logf(pp);              // softplus(dtv)
            }
            float sz = zz[j] / (1.f + __expf(-zz[j]));
            g_coef[(size_t)(R0 + row) * DII + q * 4 + j] =
                make_float4(delta * uu[j], pp, sz, uu[j] * Dvs[j]);
        }
    }
}

// ---------------- fused out_proj GEMM + residual + LayerNorm ----------------
__global__ void __launch_bounds__(256) outproj_ln_kernel(
    const float* __restrict__ A, const float* __restrict__ B,
    const float* __restrict__ nw, const float* __restrict__ nb)
{
    const int BK = 16, K = DII;
    __shared__ float As[2][64][BK + 4];
    __shared__ float Bs[2][DMM][BK + 4];
    __shared__ float Cs[64][DMM + 4];

    int tid  = threadIdx.x;
    int bm   = blockIdx.x * 64;
    int warp = tid >> 5, lane = tid & 31;
    int gid  = lane >> 2, tig = lane & 3;
    int m0   = (warp & 1) * 32;
    int n0   = (warp >> 1) * 32;

    float acc[2][4][4];
    #pragma unroll
    for (int i = 0; i < 2; i++)
        #pragma unroll
        for (int j = 0; j < 4; j++)
            #pragma unroll
            for (int k = 0; k < 4; k++) acc[i][j][k] = 0.f;

    int arow = tid >> 2, akq = (tid & 3) * 4;
    int brow = tid >> 1, bkq = (tid & 1) * 8;
    const float* aptr = A + (size_t)(bm + arow) * K + akq;
    const float* bptr = B + (size_t)brow * K + bkq;
    const int nk = K / BK;

    {
        uint32_t da  = smem_u32(&As[0][arow][akq]);
        uint32_t db0 = smem_u32(&Bs[0][brow][bkq]);
        uint32_t db1 = smem_u32(&Bs[0][brow][bkq + 4]);
        asm volatile("cp.async.cg.shared.global [%0], [%1], 16;" :: "r"(da),  "l"(aptr));
        asm volatile("cp.async.cg.shared.global [%0], [%1], 16;" :: "r"(db0), "l"(bptr));
        asm volatile("cp.async.cg.shared.global [%0], [%1], 16;" :: "r"(db1), "l"(bptr + 4));
        asm volatile("cp.async.commit_group;");
    }

    for (int i = 0; i < nk; i++) {
        int buf = i & 1;
        asm volatile("cp.async.wait_group 0;");
        __syncthreads();
        if (i + 1 < nk) {
            int k0 = (i + 1) * BK;
            uint32_t da  = smem_u32(&As[buf ^ 1][arow][akq]);
            uint32_t db0 = smem_u32(&Bs[buf ^ 1][brow][bkq]);
            uint32_t db1 = smem_u32(&Bs[buf ^ 1][brow][bkq + 4]);
            asm volatile("cp.async.cg.shared.global [%0], [%1], 16;" :: "r"(da),  "l"(aptr + k0));
            asm volatile("cp.async.cg.shared.global [%0], [%1], 16;" :: "r"(db0), "l"(bptr + k0));
            asm volatile("cp.async.cg.shared.global [%0], [%1], 16;" :: "r"(db1), "l"(bptr + k0 + 4));
            asm volatile("cp.async.commit_group;");
        }
        #pragma unroll
        for (int c = 0; c < 2; c++) {
            int kb = c * 8;
            uint32_t afr[2][4], bfr[4][2];
            #pragma unroll
            for (int mt = 0; mt < 2; mt++) {
                int r = m0 + mt * 16 + gid;
                afr[mt][0] = __float_as_uint(As[buf][r    ][kb + tig]);
                afr[mt][1] = __float_as_uint(As[buf][r + 8][kb + tig]);
                afr[mt][2] = __float_as_uint(As[buf][r    ][kb + tig + 4]);
                afr[mt][3] = __float_as_uint(As[buf][r + 8][kb + tig + 4]);
            }
            #pragma unroll
            for (int nt = 0; nt < 4; nt++) {
                int cn = n0 + nt * 8 + gid;
                bfr[nt][0] = __float_as_uint(Bs[buf][cn][kb + tig]);
                bfr[nt][1] = __float_as_uint(Bs[buf][cn][kb + tig + 4]);
            }
            #pragma unroll
            for (int mt = 0; mt < 2; mt++)
                #pragma unroll
                for (int nt = 0; nt < 4; nt++)
                    mma_tf32(acc[mt][nt], afr[mt], bfr[nt]);
        }
    }

    #pragma unroll
    for (int mt = 0; mt < 2; mt++) {
        int r = m0 + mt * 16 + gid;
        #pragma unroll
        for (int nt = 0; nt < 4; nt++) {
            int cn = n0 + nt * 8 + tig * 2;
            *(float2*)&Cs[r    ][cn] = make_float2(acc[mt][nt][0], acc[mt][nt][1]);
            *(float2*)&Cs[r + 8][cn] = make_float2(acc[mt][nt][2], acc[mt][nt][3]);
        }
    }
    __syncthreads();

    float w0 = nw[lane], w1 = nw[lane + 32], w2 = nw[lane + 64], w3 = nw[lane + 96];
    float b0 = nb[lane], b1 = nb[lane + 32], b2 = nb[lane + 64], b3 = nb[lane + 96];
    for (int rr = warp * 8; rr < warp * 8 + 8; rr++) {
        size_t gr = (size_t)(bm + rr) * DMM;
        float v0 = Cs[rr][lane]      + g_h[gr + lane];
        float v1 = Cs[rr][lane + 32] + g_h[gr + lane + 32];
        float v2 = Cs[rr][lane + 64] + g_h[gr + lane + 64];
        float v3 = Cs[rr][lane + 96] + g_h[gr + lane + 96];
        float s = v0 + v1 + v2 + v3;
        float q = v0 * v0 + v1 * v1 + v2 * v2 + v3 * v3;
        #pragma unroll
        for (int o = 16; o; o >>= 1) {
            s += __shfl_xor_sync(0xffffffffu, s, o);
            q += __shfl_xor_sync(0xffffffffu, q, o);
        }
        float mu = s * (1.0f / DMM);
        float var = q * (1.0f / DMM) - mu * mu;
        float rs = rsqrtf(var + LNEPS);
        g_h[gr + lane]      = (v0 - mu) * rs * w0 + b0;
        g_h[gr + lane + 32] = (v1 - mu) * rs * w1 + b1;
        g_h[gr + lane + 64] = (v2 - mu) * rs * w2 + b2;
        g_h[gr + lane + 96] = (v3 - mu) * rs * w3 + b3;
    }
}

// ---------------- selective scan: pure FFMA inner loop, coef streamed via smem ----------------
__global__ void __launch_bounds__(128) scan_kernel(const float* __restrict__ alog)
{
    extern __shared__ float sm[];
    float*  sBC = sm;                         // [256][32]  (B16 | C16) per t
    float4* scf = (float4*)(sm + TT * 32);    // [2][CHK][128]

    int n = blockIdx.x, tid = threadIdx.x;
    int d = blockIdx.y * 128 + tid;
    int dbase = blockIdx.y * 128;

    // B,C for all t (broadcast data)
    {
        const float* src = g_xdbl + (size_t)n * TT * 40;
        #pragma unroll
        for (int i = 0; i < 16; i++) {
            int idx = tid + i * 128;          // 2048 float4
            int t = idx >> 3, j = idx & 7;
            uint32_t dst = smem_u32(&sBC[t * 32 + j * 4]);
            asm volatile("cp.async.cg.shared.global [%0], [%1], 16;"
                         :: "r"(dst), "l"(src + (size_t)t * 40 + 8 + j * 4));
        }
    }
    // coef chunk 0
    #pragma unroll
    for (int r = 0; r < CHK; r++) {
        uint32_t dst = smem_u32(&scf[r * 128 + tid]);
        asm volatile("cp.async.cg.shared.global [%0], [%1], 16;"
                     :: "r"(dst), "l"(g_coef + (size_t)(n * TT + r) * DII + dbase + tid));
    }
    asm volatile("cp.async.commit_group;");

    float A[DSS];
    bool fastA = true;
    #pragma unroll
    for (int s = 0; s < DSS; s++) {
        A[s] = -__expf(alog[d * DSS + s]);
        fastA = fastA && (A[s] == -(float)(s + 1));
    }
    float hst[DSS];
    #pragma unroll
    for (int s = 0; s < DSS; s++) hst[s] = 0.f;

    size_t base_y = (size_t)n * TT * DII + d;

    asm volatile("cp.async.wait_group 0;");
    __syncthreads();

    for (int c = 0; c < TT / CHK; c++) {
        int buf = c & 1;
        if (c + 1 < TT / CHK) {
            #pragma unroll
            for (int r = 0; r < CHK; r++) {
                uint32_t dst = smem_u32(&scf[(buf ^ 1) * CHK * 128 + r * 128 + tid]);
                asm volatile("cp.async.cg.shared.global [%0], [%1], 16;"
                             :: "r"(dst),
                                "l"(g_coef + (size_t)(n * TT + (c + 1) * CHK + r) * DII + dbase + tid));
            }
            asm volatile("cp.async.commit_group;");
        }
        #pragma unroll 2
        for (int tt = 0; tt < CHK; tt++) {
            int t = c * CHK + tt;
            float4 cf = scf[buf * CHK * 128 + tt * 128 + tid];
            const float4* bc = (const float4*)(sBC + t * 32);
            float4 B0 = bc[0], B1 = bc[1], B2 = bc[2], B3 = bc[3];
            float4 C0 = bc[4], C1 = bc[5], C2 = bc[6], C3 = bc[7];
            float Bf[16] = {B0.x,B0.y,B0.z,B0.w, B1.x,B1.y,B1.z,B1.w,
                            B2.x,B2.y,B2.z,B2.w, B3.x,B3.y,B3.z,B3.w};
            float Cf[16] = {C0.x,C0.y,C0.z,C0.w, C1.x,C1.y,C1.z,C1.w,
                            C2.x,C2.y,C2.z,C2.w, C3.x,C3.y,C3.z,C3.w};
            float du = cf.x, p = cf.y, sz = cf.z, uD = cf.w;
            float e[16];
            if (fastA) {
                e[0] = p;
                e[1] = p * p;
                e[2] = e[1] * p;     e[3]  = e[1] * e[1];
                e[4] = e[3] * p;     e[5]  = e[3] * e[1];
                e[6] = e[3] * e[2];  e[7]  = e[3] * e[3];
                e[8] = e[7] * p;     e[9]  = e[7] * e[1];
                e[10] = e[7] * e[2]; e[11] = e[7] * e[3];
                e[12] = e[7] * e[4]; e[13] = e[7] * e[5];
                e[14] = e[7] * e[6]; e[15] = e[7] * e[7];
            } else {
                float delta = -__logf(p);
                #pragma unroll
                for (int s = 0; s < DSS; s++) e[s] = __expf(delta * A[s]);
            }
            float y0 = 0.f, y1 = 0.f, y2 = 0.f, y3 = 0.f;
            #pragma unroll
            for (int s = 0; s < DSS; s += 4) {
                hst[s]     = e[s]     * hst[s]     + du * Bf[s];
                hst[s + 1] = e[s + 1] * hst[s + 1] + du * Bf[s + 1];
                hst[s + 2] = e[s + 2] * hst[s + 2] + du * Bf[s + 2];
                hst[s + 3] = e[s + 3] * hst[s + 3] + du * Bf[s + 3];
                y0 += hst[s]     * Cf[s];
                y1 += hst[s + 1] * Cf[s + 1];
                y2 += hst[s + 2] * Cf[s + 2];
                y3 += hst[s + 3] * Cf[s + 3];
            }
            float y = ((y0 + y1) + (y2 + y3)) + uD;
            g_ym[base_y + (size_t)t * DII] = y * sz;
        }
        asm volatile("cp.async.wait_group 0;");
        __syncthreads();
    }
}

// ---------------- final layernorm + mean over T ----------------
__global__ void __launch_bounds__(128) final_partial_kernel(
    const float* __restrict__ w, const float* __restrict__ b)
{
    int n = blockIdx.x, t0 = blockIdx.y * 64, d = threadIdx.x;
    float wd = w[d], bd = b[d], acc = 0.f;
    for (int tt = 0; tt < 64; tt++) {
        float v = g_h[(size_t)(n * TT + t0 + tt) * DMM + d];
        float mu, var;
        row_stats128(v, mu, var);
        acc += (v - mu) * rsqrtf(var + LNEPS) * wd + bd;
    }
    g_part[(size_t)(n * 4 + blockIdx.y) * DMM + d] = acc;
}

__global__ void __launch_bounds__(128) final_combine_kernel(float* __restrict__ out)
{
    int n = blockIdx.x, d = threadIdx.x;
    float s = g_part[(size_t)(n * 4 + 0) * DMM + d]
            + g_part[(size_t)(n * 4 + 1) * DMM + d]
            + g_part[(size_t)(n * 4 + 2) * DMM + d]
            + g_part[(size_t)(n * 4 + 3) * DMM + d];
    out[(size_t)n * DMM + d] = s * (1.0f / TT);
}

// ---------------- launch ----------------
extern "C" void kernel_launch(void* const* d_in, const int* in_sizes, int n_in,
                              void* d_out, int out_size)
{
    (void)in_sizes; (void)n_in; (void)out_size;
    const float* x     = (const float*)d_in[0];
    const float* inp_w = (const float*)d_in[1];
    const float* inp_b = (const float*)d_in[2];
    const float* ipw   = (const float*)d_in[3];
    const float* cw    = (const float*)d_in[4];
    const float* cb    = (const float*)d_in[5];
    const float* xpw   = (const float*)d_in[6];
    const float* dtw   = (const float*)d_in[7];
    const float* dtb   = (const float*)d_in[8];
    const float* alog  = (const float*)d_in[9];
    const float* Dv    = (const float*)d_in[10];
    const float* opw   = (const float*)d_in[11];
    const float* nw    = (const float*)d_in[12];
    const float* nb    = (const float*)d_in[13];
    const float* onw   = (const float*)d_in[14];
    const float* onb   = (const float*)d_in[15];
    float* out = (float*)d_out;

    float *ph, *pxz, *pym;
    cudaGetSymbolAddress((void**)&ph,  g_h);
    cudaGetSymbolAddress((void**)&pxz, g_xz);
    cudaGetSymbolAddress((void**)&pym, g_ym);

    const int SMEM_IP = (64 * 68 + 128 * 68) * 4;          // 52224
    const int SMEM_CX = (64 * 260 + 40 * 260) * 4;         // 108160
    const int SMEM_SC = TT * 32 * 4 + 2 * CHK * 128 * 16;  // 32768 + 65536 = 98304
    cudaFuncSetAttribute(input_proj_mma,  cudaFuncAttributeMaxDynamicSharedMemorySize, SMEM_IP);
    cudaFuncSetAttribute(convxproj_kernel, cudaFuncAttributeMaxDynamicSharedMemorySize, SMEM_CX);
    cudaFuncSetAttribute(scan_kernel,     cudaFuncAttributeMaxDynamicSharedMemorySize, SMEM_SC);

    input_proj_mma<<<dim3(NSEQ, 4), 256, SMEM_IP>>>(x, inp_w, inp_b);

    for (int l = 0; l < 2; l++) {
        mma_gemm_kernel<<<dim3(ROWS / 64, 8), 128>>>(
            ph, ipw + (size_t)l * 2 * DII * DMM, pxz, ROWS, 2 * DII, DMM);
        convxproj_kernel<<<NSEQ * 4, 128, SMEM_CX>>>(
            xpw + (size_t)l * 40 * DII, cw + (size_t)l * DII * 4, cb + (size_t)l * DII,
            dtw + (size_t)l * DII * DTRR, dtb + (size_t)l * DII, Dv + (size_t)l * DII);
        scan_kernel<<<dim3(NSEQ, 2), 128, SMEM_SC>>>(alog + (size_t)l * DII * DSS);
        outproj_ln_kernel<<<ROWS / 64, 256>>>(
            pym, opw + (size_t)l * DMM * DII, nw + (size_t)l * DMM, nb + (size_t)l * DMM);
    }

    final_partial_kernel<<<dim3(NSEQ, 4), 128>>>(onw, onb);
    final_combine_kernel<<<NSEQ, 128>>>(out);
}